// round 3
// baseline (speedup 1.0000x reference)
#include <cuda_runtime.h>
#include <cstdint>
#include <math.h>

// Problem constants
#define B_   2
#define M_   2048
#define N_   2048
#define D_   2048
#define H_   16
#define DH_  128
#define DR_  64
#define DQK_ 192
#define SCALE_ 0.07216878364870323f  // 1/sqrt(192)

// ---------------- scratch (allocation-free: __device__ globals) ----------------
__device__ float g_Qf[(size_t)B_ * H_ * M_ * DQK_];   // (b,h,m,192) = [QC | roped QR]
__device__ float g_Kf[(size_t)B_ * H_ * N_ * DQK_];   // (b,h,n,192) = [KC | roped KR]
__device__ float g_Vf[(size_t)B_ * H_ * N_ * DH_];    // (b,h,n,128)
__device__ float g_Ao[(size_t)B_ * M_ * (H_ * DH_)];  // (b,m,h*128)
__device__ float g_cos[M_ * 32];
__device__ float g_sin[M_ * 32];

// ---------------- small PTX helpers ----------------
__device__ __forceinline__ void cp_async16(float* smem, const float* gmem) {
    uint32_t s = (uint32_t)__cvta_generic_to_shared(smem);
    asm volatile("cp.async.cg.shared.global [%0], [%1], 16;\n" :: "r"(s), "l"(gmem) : "memory");
}
__device__ __forceinline__ void cp_commit() { asm volatile("cp.async.commit_group;\n" ::: "memory"); }
template <int N> __device__ __forceinline__ void cp_wait() {
    asm volatile("cp.async.wait_group %0;\n" :: "n"(N) : "memory");
}
__device__ __forceinline__ uint32_t f2tf32(float x) {
    uint32_t r; asm("cvt.rna.tf32.f32 %0, %1;\n" : "=r"(r) : "f"(x)); return r;
}
__device__ __forceinline__ void mma_tf32(float c[4], const uint32_t a[4], const uint32_t b[2]) {
    asm volatile(
        "mma.sync.aligned.m16n8k8.row.col.f32.tf32.tf32.f32 "
        "{%0,%1,%2,%3},{%4,%5,%6,%7},{%8,%9},{%0,%1,%2,%3};\n"
        : "+f"(c[0]), "+f"(c[1]), "+f"(c[2]), "+f"(c[3])
        : "r"(a[0]), "r"(a[1]), "r"(a[2]), "r"(a[3]), "r"(b[0]), "r"(b[1]));
}

// ---------------- RoPE cache + apply ----------------
__global__ void rope_cache_kernel() {
    int idx = blockIdx.x * blockDim.x + threadIdx.x;
    if (idx >= M_ * 32) return;
    int s = idx >> 5, i = idx & 31;
    double e = (double)(2 * i) / 64.0;
    float freq = (float)(1.0 / pow(1000000.0, e));   // matches fp32 freqs to ~1 ulp
    float ang = (float)s * freq;                     // fp32 angle like jnp.outer
    double a = (double)ang;                          // exact trig of that angle
    g_cos[idx] = (float)cos(a);
    g_sin[idx] = (float)sin(a);
}

__global__ void rope_apply_kernel(float* __restrict__ buf) {
    int idx = blockIdx.x * blockDim.x + threadIdx.x;
    if (idx >= B_ * H_ * M_ * 32) return;
    int i = idx & 31;
    int s = (idx >> 5) & (M_ - 1);
    int bh = idx >> 16;
    size_t base = ((size_t)bh * M_ + s) * DQK_ + DH_ + 2 * i;
    float c = g_cos[(s << 5) + i], sn = g_sin[(s << 5) + i];
    float x0 = buf[base], x1 = buf[base + 1];
    buf[base]     = __uint_as_float(f2tf32(x0 * c - x1 * sn));
    buf[base + 1] = __uint_as_float(f2tf32(x1 * c + x0 * sn));
}

// ---------------- generic C = A @ W^T GEMM (tf32 mma, 128x128x32) ----------------
#define GBM 128
#define GBN 128
#define GBK 32
#define GST 36
#define GEMM_SMEM (2 * 2 * GBM * GST * 4)   // 73728 B

__device__ __forceinline__ void store_out(float* C, int r, int n, float v,
                                          int direct, int dh, int ld, int off) {
    if (direct) { C[(size_t)r * 2048 + n] = v; return; }
    int b = r >> 11, m = r & (M_ - 1);
    int h = n / dh, d = n - h * dh;
    C[(((size_t)(b * H_ + h) * M_) + m) * ld + d + off] = __uint_as_float(f2tf32(v));
}

__global__ __launch_bounds__(256, 2)
void gemm_tn(const float* __restrict__ A, const float* __restrict__ W,
             float* __restrict__ C, int direct, int dh, int ld, int off) {
    extern __shared__ float sm[];
    float* smA = sm;                         // [2][128*36]
    float* smB = sm + 2 * GBM * GST;         // [2][128*36]

    const int tid = threadIdx.x;
    const int m0 = blockIdx.y * GBM;
    const int n0 = blockIdx.x * GBN;
    const float* Ab = A + (size_t)m0 * D_;
    const float* Wb = W + (size_t)n0 * D_;

    auto load_tile = [&](int kt, int buf) {
        const int k0 = kt * GBK;
        float* sa = smA + buf * (GBM * GST);
        float* sb = smB + buf * (GBM * GST);
#pragma unroll
        for (int i = 0; i < 4; ++i) {
            int id = tid + i * 256;
            int row = id >> 3, c4 = (id & 7) << 2;
            cp_async16(sa + row * GST + c4, Ab + (size_t)row * D_ + k0 + c4);
        }
#pragma unroll
        for (int i = 0; i < 4; ++i) {
            int id = tid + i * 256;
            int row = id >> 3, c4 = (id & 7) << 2;
            cp_async16(sb + row * GST + c4, Wb + (size_t)row * D_ + k0 + c4);
        }
        cp_commit();
    };

    float acc[4][4][4];
#pragma unroll
    for (int a = 0; a < 4; ++a)
#pragma unroll
        for (int b = 0; b < 4; ++b)
#pragma unroll
            for (int c = 0; c < 4; ++c) acc[a][b][c] = 0.f;

    const int warp = tid >> 5, lane = tid & 31;
    const int wm = warp >> 2, wn = warp & 3;   // 2 x 4 warp grid; warp tile 64x32
    const int g = lane >> 2, t = lane & 3;

    load_tile(0, 0);
    const int NKT = D_ / GBK;  // 64
    for (int kt = 0; kt < NKT; ++kt) {
        int cur = kt & 1;
        if (kt + 1 < NKT) { load_tile(kt + 1, cur ^ 1); cp_wait<1>(); }
        else              { cp_wait<0>(); }
        __syncthreads();
        const float* sa = smA + cur * (GBM * GST);
        const float* sb = smB + cur * (GBM * GST);
#pragma unroll
        for (int kk = 0; kk < GBK; kk += 8) {
            uint32_t af[4][4], bf[4][2];
#pragma unroll
            for (int im = 0; im < 4; ++im) {
                const float* p0 = sa + (wm * 64 + im * 16 + g) * GST + kk + t;
                const float* p1 = p0 + 8 * GST;
                af[im][0] = f2tf32(p0[0]); af[im][2] = f2tf32(p0[4]);
                af[im][1] = f2tf32(p1[0]); af[im][3] = f2tf32(p1[4]);
            }
#pragma unroll
            for (int in = 0; in < 4; ++in) {
                const float* p = sb + (wn * 32 + in * 8 + g) * GST + kk + t;
                bf[in][0] = f2tf32(p[0]); bf[in][1] = f2tf32(p[4]);
            }
#pragma unroll
            for (int im = 0; im < 4; ++im)
#pragma unroll
                for (int in = 0; in < 4; ++in)
                    mma_tf32(acc[im][in], af[im], bf[in]);
        }
        __syncthreads();
    }

#pragma unroll
    for (int im = 0; im < 4; ++im) {
        int r0 = m0 + wm * 64 + im * 16 + g;
#pragma unroll
        for (int in = 0; in < 4; ++in) {
            int c0 = n0 + wn * 32 + in * 8 + 2 * t;
            store_out(C, r0,     c0,     acc[im][in][0], direct, dh, ld, off);
            store_out(C, r0,     c0 + 1, acc[im][in][1], direct, dh, ld, off);
            store_out(C, r0 + 8, c0,     acc[im][in][2], direct, dh, ld, off);
            store_out(C, r0 + 8, c0 + 1, acc[im][in][3], direct, dh, ld, off);
        }
    }
}

// ---------------- fused flash attention (Br=Bc=64, d=192, dv=128) ----------------
#define QST 196
#define VST 136
#define PST 68
#define FLASH_SMEM ((64 * QST * 2 + 64 * VST + 64 * PST + 64 * 3 + 128 * 2) * 4)  // 154368 B

__global__ __launch_bounds__(256, 1)
void flash_kernel() {
    extern __shared__ float sm[];
    float* Qs = sm;                    // 64 x 196
    float* Ks = Qs + 64 * QST;         // 64 x 196
    float* Vs = Ks + 64 * QST;         // 64 x 136
    float* Ps = Vs + 64 * VST;         // 64 x 68
    float* row_m  = Ps + 64 * PST;     // 64
    float* row_l  = row_m + 64;        // 64
    float* row_sc = row_l + 64;        // 64
    float* red    = row_sc + 64;       // 64 x 2
    float* red2   = red + 128;         // 64 x 2

    const int tid = threadIdx.x;
    const int m0 = blockIdx.x * 64;
    const int bh = blockIdx.y;
    const int b = bh >> 4, h = bh & 15;

    const float* Qg = g_Qf + ((size_t)bh * M_ + m0) * DQK_;
    const float* Kg = g_Kf + (size_t)bh * N_ * DQK_;
    const float* Vg = g_Vf + (size_t)bh * N_ * DH_;

#pragma unroll
    for (int i = 0; i < 12; ++i) {
        int id = tid + i * 256;
        int row = id / 48, c4 = (id % 48) << 2;
        cp_async16(Qs + row * QST + c4, Qg + (size_t)row * DQK_ + c4);
    }
    cp_commit();
    if (tid < 64) { row_m[tid] = -1e30f; row_l[tid] = 0.f; }

    float o[8][4];
#pragma unroll
    for (int i = 0; i < 8; ++i)
#pragma unroll
        for (int j = 0; j < 4; ++j) o[i][j] = 0.f;

    const int warp = tid >> 5, lane = tid & 31;
    const int wm = warp >> 1, wn = warp & 1;   // S: 4x2 warp grid (16x32); PV: 16x64
    const int g = lane >> 2, t = lane & 3;
    const int r0 = wm * 16 + g;

    cp_wait<0>();
    __syncthreads();

    for (int j = 0; j < N_ / 64; ++j) {
        const float* Kt = Kg + (size_t)j * 64 * DQK_;
        const float* Vt = Vg + (size_t)j * 64 * DH_;
#pragma unroll
        for (int i = 0; i < 12; ++i) {
            int id = tid + i * 256;
            int row = id / 48, c4 = (id % 48) << 2;
            cp_async16(Ks + row * QST + c4, Kt + (size_t)row * DQK_ + c4);
        }
#pragma unroll
        for (int i = 0; i < 8; ++i) {
            int id = tid + i * 256;
            int row = id >> 5, c4 = (id & 31) << 2;
            cp_async16(Vs + row * VST + c4, Vt + (size_t)row * DH_ + c4);
        }
        cp_commit();
        cp_wait<0>();
        __syncthreads();

        // ---- S = Q K^T (warp tile 16x32), values already tf32-rounded in gmem ----
        float s[4][4];
#pragma unroll
        for (int a = 0; a < 4; ++a)
#pragma unroll
            for (int c = 0; c < 4; ++c) s[a][c] = 0.f;
#pragma unroll
        for (int kk = 0; kk < DQK_; kk += 8) {
            uint32_t af[4];
            const float* p0 = Qs + r0 * QST + kk + t;
            const float* p1 = p0 + 8 * QST;
            af[0] = __float_as_uint(p0[0]); af[2] = __float_as_uint(p0[4]);
            af[1] = __float_as_uint(p1[0]); af[3] = __float_as_uint(p1[4]);
#pragma unroll
            for (int nf = 0; nf < 4; ++nf) {
                const float* p = Ks + (wn * 32 + nf * 8 + g) * QST + kk + t;
                uint32_t bf[2] = { __float_as_uint(p[0]), __float_as_uint(p[4]) };
                mma_tf32(s[nf], af, bf);
            }
        }

        // ---- online softmax ----
        float mx0 = -1e30f, mx1 = -1e30f;
#pragma unroll
        for (int nf = 0; nf < 4; ++nf) {
            s[nf][0] *= SCALE_; s[nf][1] *= SCALE_; s[nf][2] *= SCALE_; s[nf][3] *= SCALE_;
            mx0 = fmaxf(mx0, fmaxf(s[nf][0], s[nf][1]));
            mx1 = fmaxf(mx1, fmaxf(s[nf][2], s[nf][3]));
        }
        mx0 = fmaxf(mx0, __shfl_xor_sync(0xffffffffu, mx0, 1));
        mx0 = fmaxf(mx0, __shfl_xor_sync(0xffffffffu, mx0, 2));
        mx1 = fmaxf(mx1, __shfl_xor_sync(0xffffffffu, mx1, 1));
        mx1 = fmaxf(mx1, __shfl_xor_sync(0xffffffffu, mx1, 2));
        if (t == 0) { red[r0 * 2 + wn] = mx0; red[(r0 + 8) * 2 + wn] = mx1; }
        __syncthreads();
        if (tid < 64) {
            float nm = fmaxf(row_m[tid], fmaxf(red[2 * tid], red[2 * tid + 1]));
            row_sc[tid] = __expf(row_m[tid] - nm);
            row_m[tid] = nm;
        }
        __syncthreads();
        float m0r = row_m[r0], m1r = row_m[r0 + 8];
        float sum0 = 0.f, sum1 = 0.f;
#pragma unroll
        for (int nf = 0; nf < 4; ++nf) {
            float p0 = __expf(s[nf][0] - m0r), p1 = __expf(s[nf][1] - m0r);
            float p2 = __expf(s[nf][2] - m1r), p3 = __expf(s[nf][3] - m1r);
            sum0 += p0 + p1; sum1 += p2 + p3;
            int c = wn * 32 + nf * 8 + 2 * t;
            Ps[r0 * PST + c]           = __uint_as_float(f2tf32(p0));
            Ps[r0 * PST + c + 1]       = __uint_as_float(f2tf32(p1));
            Ps[(r0 + 8) * PST + c]     = __uint_as_float(f2tf32(p2));
            Ps[(r0 + 8) * PST + c + 1] = __uint_as_float(f2tf32(p3));
        }
        sum0 += __shfl_xor_sync(0xffffffffu, sum0, 1);
        sum0 += __shfl_xor_sync(0xffffffffu, sum0, 2);
        sum1 += __shfl_xor_sync(0xffffffffu, sum1, 1);
        sum1 += __shfl_xor_sync(0xffffffffu, sum1, 2);
        if (t == 0) { red2[r0 * 2 + wn] = sum0; red2[(r0 + 8) * 2 + wn] = sum1; }
        float sc0 = row_sc[r0], sc1 = row_sc[r0 + 8];
#pragma unroll
        for (int nf = 0; nf < 8; ++nf) {
            o[nf][0] *= sc0; o[nf][1] *= sc0; o[nf][2] *= sc1; o[nf][3] *= sc1;
        }
        __syncthreads();
        if (tid < 64)
            row_l[tid] = row_l[tid] * row_sc[tid] + red2[2 * tid] + red2[2 * tid + 1];

        // ---- O += P @ V (warp tile 16x64) ----
#pragma unroll
        for (int kk = 0; kk < 64; kk += 8) {
            uint32_t af[4];
            const float* p0 = Ps + r0 * PST + kk + t;
            const float* p1 = p0 + 8 * PST;
            af[0] = __float_as_uint(p0[0]); af[2] = __float_as_uint(p0[4]);
            af[1] = __float_as_uint(p1[0]); af[3] = __float_as_uint(p1[4]);
#pragma unroll
            for (int nf = 0; nf < 8; ++nf) {
                const float* pv = Vs + (kk + t) * VST + wn * 64 + nf * 8 + g;
                uint32_t bf[2] = { __float_as_uint(pv[0]), __float_as_uint(pv[4 * VST]) };
                mma_tf32(o[nf], af, bf);
            }
        }
        __syncthreads();
    }

    float inv0 = 1.f / row_l[r0];
    float inv1 = 1.f / row_l[r0 + 8];
#pragma unroll
    for (int nf = 0; nf < 8; ++nf) {
        int c = h * DH_ + wn * 64 + nf * 8 + 2 * t;
        size_t base0 = ((size_t)(b * M_) + m0 + r0) * (H_ * DH_) + c;
        size_t base1 = base0 + (size_t)8 * (H_ * DH_);
        g_Ao[base0]     = o[nf][0] * inv0;
        g_Ao[base0 + 1] = o[nf][1] * inv0;
        g_Ao[base1]     = o[nf][2] * inv1;
        g_Ao[base1 + 1] = o[nf][3] * inv1;
    }
}

// ---------------- launch ----------------
extern "C" void kernel_launch(void* const* d_in, const int* in_sizes, int n_in,
                              void* d_out, int out_size) {
    const float* query = (const float*)d_in[0];
    const float* keyv  = (const float*)d_in[1];
    const float* W_QC  = (const float*)d_in[2];
    const float* W_KC  = (const float*)d_in[3];
    const float* W_QR  = (const float*)d_in[4];
    const float* W_KR  = (const float*)d_in[5];
    const float* W_V   = (const float*)d_in[6];
    const float* W_O   = (const float*)d_in[7];
    float* out = (float*)d_out;

    static float *pQf = nullptr, *pKf = nullptr, *pVf = nullptr, *pAo = nullptr;
    if (!pQf) {
        cudaFuncSetAttribute(gemm_tn, cudaFuncAttributeMaxDynamicSharedMemorySize, GEMM_SMEM);
        cudaFuncSetAttribute(flash_kernel, cudaFuncAttributeMaxDynamicSharedMemorySize, FLASH_SMEM);
        cudaGetSymbolAddress((void**)&pQf, g_Qf);
        cudaGetSymbolAddress((void**)&pKf, g_Kf);
        cudaGetSymbolAddress((void**)&pVf, g_Vf);
        cudaGetSymbolAddress((void**)&pAo, g_Ao);
    }

    rope_cache_kernel<<<256, 256>>>();
    dim3 thr(256);
    // projections: rows = B*M = 4096 -> grid.y = 32
    gemm_tn<<<dim3(16, 32), thr, GEMM_SMEM>>>(query, W_QC, pQf, 0, 128, 192, 0);
    gemm_tn<<<dim3(8, 32),  thr, GEMM_SMEM>>>(query, W_QR, pQf, 0, 64, 192, 128);
    gemm_tn<<<dim3(16, 32), thr, GEMM_SMEM>>>(keyv,  W_KC, pKf, 0, 128, 192, 0);
    gemm_tn<<<dim3(8, 32),  thr, GEMM_SMEM>>>(keyv,  W_KR, pKf, 0, 64, 192, 128);
    gemm_tn<<<dim3(16, 32), thr, GEMM_SMEM>>>(keyv,  W_V,  pVf, 0, 128, 128, 0);
    rope_apply_kernel<<<8192, 256>>>(pQf);
    rope_apply_kernel<<<8192, 256>>>(pKf);
    flash_kernel<<<dim3(32, 32), thr, FLASH_SMEM>>>();
    gemm_tn<<<dim3(16, 32), thr, GEMM_SMEM>>>(pAo, W_O, out, 1, 1, 0, 0);
}

// round 5
// speedup vs baseline: 1.1285x; 1.1285x over previous
#include <cuda_runtime.h>
#include <cstdint>
#include <math.h>

// Problem constants
#define B_   2
#define M_   2048
#define N_   2048
#define D_   2048
#define H_   16
#define DH_  128
#define DR_  64
#define DQK_ 192
#define SCALE_ 0.07216878364870323f  // 1/sqrt(192)

// ---------------- scratch (allocation-free: __device__ globals) ----------------
__device__ float g_Qf[(size_t)B_ * H_ * M_ * DQK_];   // (b,h,m,192) = [QC | roped QR]
__device__ float g_Kf[(size_t)B_ * H_ * N_ * DQK_];   // (b,h,n,192)
__device__ float g_Vt[(size_t)B_ * H_ * DH_ * N_];    // V transposed: (b,h,d,n)
__device__ float g_Ao[(size_t)B_ * M_ * (H_ * DH_)];  // staging: V proj (b,h,n,d), then attn out (b,m,h*128)
__device__ float g_Aq [(size_t)B_ * M_ * D_];         // tf32-rounded query
__device__ float g_Akv[(size_t)B_ * N_ * D_];         // tf32-rounded key_value
__device__ float g_Wqc[(size_t)H_ * DH_ * D_];
__device__ float g_Wkc[(size_t)H_ * DH_ * D_];
__device__ float g_Wqr[(size_t)H_ * DR_ * D_];
__device__ float g_Wkr[(size_t)H_ * DR_ * D_];
__device__ float g_Wv [(size_t)H_ * DH_ * D_];
__device__ float g_Wo [(size_t)D_ * H_ * DH_];
__device__ float g_cos[M_ * 32];
__device__ float g_sin[M_ * 32];

// ---------------- small PTX helpers ----------------
__device__ __forceinline__ void cp_async16(float* smem, const float* gmem) {
    uint32_t s = (uint32_t)__cvta_generic_to_shared(smem);
    asm volatile("cp.async.cg.shared.global [%0], [%1], 16;\n" :: "r"(s), "l"(gmem) : "memory");
}
__device__ __forceinline__ void cp_commit() { asm volatile("cp.async.commit_group;\n" ::: "memory"); }
template <int N> __device__ __forceinline__ void cp_wait() {
    asm volatile("cp.async.wait_group %0;\n" :: "n"(N) : "memory");
}
__device__ __forceinline__ uint32_t f2tf32(float x) {
    uint32_t r; asm("cvt.rna.tf32.f32 %0, %1;\n" : "=r"(r) : "f"(x)); return r;
}
__device__ __forceinline__ uint32_t f_u(float x) { return __float_as_uint(x); }
__device__ __forceinline__ void mma_tf32(float c[4], const uint32_t a[4], const uint32_t b[2]) {
    asm volatile(
        "mma.sync.aligned.m16n8k8.row.col.f32.tf32.tf32.f32 "
        "{%0,%1,%2,%3},{%4,%5,%6,%7},{%8,%9},{%0,%1,%2,%3};\n"
        : "+f"(c[0]), "+f"(c[1]), "+f"(c[2]), "+f"(c[3])
        : "r"(a[0]), "r"(a[1]), "r"(a[2]), "r"(a[3]), "r"(b[0]), "r"(b[1]));
}

// ---------------- tf32 pre-rounding pass ----------------
__global__ void round_kernel(const float4* __restrict__ s, float4* __restrict__ d, int n4) {
    int i = blockIdx.x * blockDim.x + threadIdx.x;
    if (i >= n4) return;
    float4 v = s[i];
    v.x = __uint_as_float(f2tf32(v.x));
    v.y = __uint_as_float(f2tf32(v.y));
    v.z = __uint_as_float(f2tf32(v.z));
    v.w = __uint_as_float(f2tf32(v.w));
    d[i] = v;
}

// ---------------- RoPE cache + apply ----------------
__global__ void rope_cache_kernel() {
    int idx = blockIdx.x * blockDim.x + threadIdx.x;
    if (idx >= M_ * 32) return;
    int s = idx >> 5, i = idx & 31;
    double e = (double)(2 * i) / 64.0;
    float freq = (float)(1.0 / pow(1000000.0, e));
    float ang = (float)s * freq;
    double a = (double)ang;
    g_cos[idx] = (float)cos(a);
    g_sin[idx] = (float)sin(a);
}

__global__ void rope_apply_kernel(float* __restrict__ buf) {
    int idx = blockIdx.x * blockDim.x + threadIdx.x;
    if (idx >= B_ * H_ * M_ * 32) return;
    int i = idx & 31;
    int s = (idx >> 5) & (M_ - 1);
    int bh = idx >> 16;
    size_t base = ((size_t)bh * M_ + s) * DQK_ + DH_ + 2 * i;
    float c = g_cos[(s << 5) + i], sn = g_sin[(s << 5) + i];
    float x0 = buf[base], x1 = buf[base + 1];
    buf[base]     = __uint_as_float(f2tf32(x0 * c - x1 * sn));
    buf[base + 1] = __uint_as_float(f2tf32(x1 * c + x0 * sn));
}

// ---------------- V transpose: (b,h,n,d) -> (b,h,d,n) ----------------
__global__ void transpose_v_kernel() {
    __shared__ float tile[32][33];
    int bh = blockIdx.z;
    int d0 = blockIdx.x * 32, n0 = blockIdx.y * 32;
    const float* src = g_Ao + (size_t)bh * N_ * DH_;
    float* dst = g_Vt + (size_t)bh * DH_ * N_;
    int tx = threadIdx.x, ty = threadIdx.y;
#pragma unroll
    for (int i = 0; i < 32; i += 8)
        tile[ty + i][tx] = src[(size_t)(n0 + ty + i) * DH_ + d0 + tx];
    __syncthreads();
#pragma unroll
    for (int i = 0; i < 32; i += 8)
        dst[(size_t)(d0 + ty + i) * N_ + n0 + tx] = tile[tx][ty + i];
}

// ---------------- GEMM: C = A @ W^T  (tf32 mma, 128x128x32, 3-stage) ----------------
// A, W pre-rounded to tf32. k-slot permutation: within each 16-k block, mma step
// j (0,1), slot s: k = 4*(s%4) + 2*j + (s/4). So thread t's frag = one float4.
#define GS (128 * 32)
#define STAGES 3
#define GEMM_SMEM (2 * STAGES * GS * 4)  // 98304 B

__device__ __forceinline__ void store_out(float* C, int r, int n, float v,
                                          int direct, int dh, int ld, int off) {
    if (direct) { C[(size_t)r * 2048 + n] = v; return; }
    int b = r >> 11, m = r & (M_ - 1);
    int h = n / dh, d = n - h * dh;
    C[(((size_t)(b * H_ + h) * M_) + m) * ld + d + off] = __uint_as_float(f2tf32(v));
}

__global__ __launch_bounds__(256, 2)
void gemm_tn(const float* __restrict__ A, const float* __restrict__ W,
             float* __restrict__ C, int direct, int dh, int ld, int off) {
    extern __shared__ float sm[];
    float* smA = sm;
    float* smB = sm + STAGES * GS;

    const int tid = threadIdx.x;
    const int m0 = blockIdx.y * 128;
    const int n0 = blockIdx.x * 128;
    const float* Ab = A + (size_t)m0 * D_;
    const float* Wb = W + (size_t)n0 * D_;

    auto load_tile = [&](int kt, int buf) {
        const int k0 = kt * 32;
        float* sa = smA + buf * GS;
        float* sb = smB + buf * GS;
#pragma unroll
        for (int i = 0; i < 4; ++i) {
            int id = tid + i * 256;
            int row = id >> 3, c = id & 7;
            int phys = c ^ ((row & 1) << 2);
            cp_async16(sa + row * 32 + phys * 4, Ab + (size_t)row * D_ + k0 + c * 4);
        }
#pragma unroll
        for (int i = 0; i < 4; ++i) {
            int id = tid + i * 256;
            int row = id >> 3, c = id & 7;
            int phys = c ^ ((row & 1) << 2);
            cp_async16(sb + row * 32 + phys * 4, Wb + (size_t)row * D_ + k0 + c * 4);
        }
        cp_commit();
    };

    float acc[4][4][4] = {};

    const int warp = tid >> 5, lane = tid & 31;
    const int wm = warp >> 2, wn = warp & 3;     // 2x4 warp grid, warp tile 64x32
    const int g = lane >> 2, t = lane & 3;
    const int sw = (g & 1) << 2;                 // row parity == g&1 for all frag rows
    const int c0 = t ^ sw;

    load_tile(0, 0);
    load_tile(1, 1);
    const int NKT = D_ / 32;  // 64
    for (int kt = 0; kt < NKT; ++kt) {
        int cur = kt % 3;
        if (kt + 2 < NKT) { load_tile(kt + 2, (kt + 2) % 3); cp_wait<2>(); }
        else if (kt + 1 < NKT) cp_wait<1>();
        else cp_wait<0>();
        __syncthreads();
        const float4* sa = (const float4*)(smA + cur * GS);
        const float4* sb = (const float4*)(smB + cur * GS);
#pragma unroll
        for (int blk = 0; blk < 2; ++blk) {
            int cc = c0 ^ (blk << 2);
            float4 af[4][2];
#pragma unroll
            for (int im = 0; im < 4; ++im) {
                int r = wm * 64 + im * 16 + g;
                af[im][0] = sa[r * 8 + cc];
                af[im][1] = sa[(r + 8) * 8 + cc];
            }
#pragma unroll
            for (int in = 0; in < 4; ++in) {
                int rb = wn * 32 + in * 8 + g;
                float4 bq = sb[rb * 8 + cc];
                uint32_t b0[2] = { f_u(bq.x), f_u(bq.y) };
                uint32_t b1[2] = { f_u(bq.z), f_u(bq.w) };
#pragma unroll
                for (int im = 0; im < 4; ++im) {
                    uint32_t a0[4] = { f_u(af[im][0].x), f_u(af[im][1].x),
                                       f_u(af[im][0].y), f_u(af[im][1].y) };
                    mma_tf32(acc[im][in], a0, b0);
                    uint32_t a1[4] = { f_u(af[im][0].z), f_u(af[im][1].z),
                                       f_u(af[im][0].w), f_u(af[im][1].w) };
                    mma_tf32(acc[im][in], a1, b1);
                }
            }
        }
        __syncthreads();
    }

#pragma unroll
    for (int im = 0; im < 4; ++im) {
        int r0 = m0 + wm * 64 + im * 16 + g;
#pragma unroll
        for (int in = 0; in < 4; ++in) {
            int col = n0 + wn * 32 + in * 8 + 2 * t;
            store_out(C, r0,     col,     acc[im][in][0], direct, dh, ld, off);
            store_out(C, r0,     col + 1, acc[im][in][1], direct, dh, ld, off);
            store_out(C, r0 + 8, col,     acc[im][in][2], direct, dh, ld, off);
            store_out(C, r0 + 8, col + 1, acc[im][in][3], direct, dh, ld, off);
        }
    }
}

// ---------------- fused flash attention (Br=Bc=64, d=192, dv=128) ----------------
// smem floats: Q 12288 | K double 2*12288 | Vt 8192 | P 4096 | misc 448
#define FL_K   12288
#define FL_V   36864
#define FL_P   45056
#define FL_MISC 49152
#define FLASH_SMEM ((FL_MISC + 448) * 4)  // 198400 B

__global__ __launch_bounds__(256, 1)
void flash_kernel() {
    extern __shared__ float sm[];
    float* Qs = sm;
    float* Ks = sm + FL_K;          // two buffers of 12288
    float* Vs = sm + FL_V;          // Vt tile: 128 d-rows x 64 kv
    float* Ps = sm + FL_P;          // 64 x 64
    float* row_m  = sm + FL_MISC;
    float* row_l  = row_m + 64;
    float* row_sc = row_l + 64;
    float* red    = row_sc + 64;    // 64 x 2
    float* red2   = red + 128;      // 64 x 2

    const int tid = threadIdx.x;
    const int m0 = blockIdx.x * 64;
    const int bh = blockIdx.y;
    const int b = bh >> 4, h = bh & 15;

    const float* Qg = g_Qf + ((size_t)bh * M_ + m0) * DQK_;
    const float* Kg = g_Kf + (size_t)bh * N_ * DQK_;
    const float* Vg = g_Vt + (size_t)bh * DH_ * N_;

    auto load_K = [&](int j, int buf) {
        const float* src = Kg + (size_t)j * 64 * DQK_;
        float* dst = Ks + buf * 12288;
#pragma unroll
        for (int i = 0; i < 12; ++i) {
            int id = tid + i * 256;
            int row = id / 48, c = id % 48;
            int phys = c ^ ((row & 1) << 2);
            cp_async16(dst + row * 192 + phys * 4, src + (size_t)row * DQK_ + c * 4);
        }
        cp_commit();
    };
    auto load_V = [&](int j) {
#pragma unroll
        for (int i = 0; i < 8; ++i) {
            int id = tid + i * 256;
            int row = id >> 4, c = id & 15;
            int phys = c ^ ((row & 1) << 2);
            cp_async16(Vs + row * 64 + phys * 4, Vg + (size_t)row * N_ + j * 64 + c * 4);
        }
        cp_commit();
    };

    // Q load (group 0)
#pragma unroll
    for (int i = 0; i < 12; ++i) {
        int id = tid + i * 256;
        int row = id / 48, c = id % 48;
        int phys = c ^ ((row & 1) << 2);
        cp_async16(Qs + row * 192 + phys * 4, Qg + (size_t)row * DQK_ + c * 4);
    }
    cp_commit();
    load_K(0, 0);
    load_V(0);
    if (tid < 64) { row_m[tid] = -1e30f; row_l[tid] = 0.f; }

    float o[8][4] = {};
    const int warp = tid >> 5, lane = tid & 31;
    const int wm = warp >> 1, wn = warp & 1;   // S: 4x2 warps (16x32); PV: 16x64
    const int g = lane >> 2, t = lane & 3;
    const int r0 = wm * 16 + g;
    const int sw = (g & 1) << 2;
    const float4* Qs4 = (const float4*)Qs;
    const float4* Vs4 = (const float4*)Vs;
    const float4* Ps4 = (const float4*)Ps;

    for (int j = 0; j < N_ / 64; ++j) {
        const int cur = j & 1;
        const bool more = (j + 1 < N_ / 64);
        if (more) { load_K(j + 1, cur ^ 1); cp_wait<2>(); }
        else      { cp_wait<1>(); }
        __syncthreads();
        const float4* Ks4 = (const float4*)(Ks + cur * 12288);

        // ---- S = Q K^T (12 blocks of 16-k) ----
        float s[4][4] = {};
#pragma unroll
        for (int blk = 0; blk < 12; ++blk) {
            int cc = (blk * 4 + t) ^ sw;
            float4 q0 = Qs4[r0 * 48 + cc];
            float4 q1 = Qs4[(r0 + 8) * 48 + cc];
            uint32_t a0[4] = { f_u(q0.x), f_u(q1.x), f_u(q0.y), f_u(q1.y) };
            uint32_t a1[4] = { f_u(q0.z), f_u(q1.z), f_u(q0.w), f_u(q1.w) };
#pragma unroll
            for (int nf = 0; nf < 4; ++nf) {
                int rb = wn * 32 + nf * 8 + g;
                float4 kq = Ks4[rb * 48 + cc];
                uint32_t b0[2] = { f_u(kq.x), f_u(kq.y) };
                uint32_t b1[2] = { f_u(kq.z), f_u(kq.w) };
                mma_tf32(s[nf], a0, b0);
                mma_tf32(s[nf], a1, b1);
            }
        }

        // ---- online softmax ----
        float mx0 = -1e30f, mx1 = -1e30f;
#pragma unroll
        for (int nf = 0; nf < 4; ++nf) {
            s[nf][0] *= SCALE_; s[nf][1] *= SCALE_; s[nf][2] *= SCALE_; s[nf][3] *= SCALE_;
            mx0 = fmaxf(mx0, fmaxf(s[nf][0], s[nf][1]));
            mx1 = fmaxf(mx1, fmaxf(s[nf][2], s[nf][3]));
        }
        mx0 = fmaxf(mx0, __shfl_xor_sync(0xffffffffu, mx0, 1));
        mx0 = fmaxf(mx0, __shfl_xor_sync(0xffffffffu, mx0, 2));
        mx1 = fmaxf(mx1, __shfl_xor_sync(0xffffffffu, mx1, 1));
        mx1 = fmaxf(mx1, __shfl_xor_sync(0xffffffffu, mx1, 2));
        if (t == 0) { red[r0 * 2 + wn] = mx0; red[(r0 + 8) * 2 + wn] = mx1; }
        __syncthreads();
        if (tid < 64) {
            float nm = fmaxf(row_m[tid], fmaxf(red[2 * tid], red[2 * tid + 1]));
            row_sc[tid] = __expf(row_m[tid] - nm);
            row_m[tid] = nm;
        }
        __syncthreads();
        float m0r = row_m[r0], m1r = row_m[r0 + 8];
        float sum0 = 0.f, sum1 = 0.f;
#pragma unroll
        for (int nf = 0; nf < 4; ++nf) {
            float p0 = __expf(s[nf][0] - m0r), p1 = __expf(s[nf][1] - m0r);
            float p2 = __expf(s[nf][2] - m1r), p3 = __expf(s[nf][3] - m1r);
            sum0 += p0 + p1; sum1 += p2 + p3;
            int c = wn * 32 + nf * 8 + 2 * t;
            int chunk = c >> 2, pos = c & 3;
            float2 w0 = { __uint_as_float(f2tf32(p0)), __uint_as_float(f2tf32(p1)) };
            float2 w1 = { __uint_as_float(f2tf32(p2)), __uint_as_float(f2tf32(p3)) };
            *(float2*)&Ps[r0 * 64 + (chunk ^ sw) * 4 + pos] = w0;
            *(float2*)&Ps[(r0 + 8) * 64 + (chunk ^ sw) * 4 + pos] = w1;
        }
        sum0 += __shfl_xor_sync(0xffffffffu, sum0, 1);
        sum0 += __shfl_xor_sync(0xffffffffu, sum0, 2);
        sum1 += __shfl_xor_sync(0xffffffffu, sum1, 1);
        sum1 += __shfl_xor_sync(0xffffffffu, sum1, 2);
        if (t == 0) { red2[r0 * 2 + wn] = sum0; red2[(r0 + 8) * 2 + wn] = sum1; }
        float sc0 = row_sc[r0], sc1 = row_sc[r0 + 8];
#pragma unroll
        for (int nf = 0; nf < 8; ++nf) {
            o[nf][0] *= sc0; o[nf][1] *= sc0; o[nf][2] *= sc1; o[nf][3] *= sc1;
        }
        if (more) cp_wait<1>(); else cp_wait<0>();   // V(j) done (K(j+1) may fly)
        __syncthreads();
        if (tid < 64)
            row_l[tid] = row_l[tid] * row_sc[tid] + red2[2 * tid] + red2[2 * tid + 1];

        // ---- O += P @ V^T-tile (4 blocks of 16-kv) ----
#pragma unroll
        for (int blk = 0; blk < 4; ++blk) {
            int cc = (blk * 4 + t) ^ sw;
            float4 p0 = Ps4[r0 * 16 + cc];
            float4 p1 = Ps4[(r0 + 8) * 16 + cc];
            uint32_t a0[4] = { f_u(p0.x), f_u(p1.x), f_u(p0.y), f_u(p1.y) };
            uint32_t a1[4] = { f_u(p0.z), f_u(p1.z), f_u(p0.w), f_u(p1.w) };
#pragma unroll
            for (int nf = 0; nf < 8; ++nf) {
                int rd = wn * 64 + nf * 8 + g;
                float4 vq = Vs4[rd * 16 + cc];
                uint32_t b0[2] = { f_u(vq.x), f_u(vq.y) };
                uint32_t b1[2] = { f_u(vq.z), f_u(vq.w) };
                mma_tf32(o[nf], a0, b0);
                mma_tf32(o[nf], a1, b1);
            }
        }
        __syncthreads();
        if (more) load_V(j + 1);
    }

    float inv0 = 1.f / row_l[r0];
    float inv1 = 1.f / row_l[r0 + 8];
#pragma unroll
    for (int nf = 0; nf < 8; ++nf) {
        int c = h * DH_ + wn * 64 + nf * 8 + 2 * t;
        size_t base0 = ((size_t)(b * M_) + m0 + r0) * (H_ * DH_) + c;
        size_t base1 = base0 + (size_t)8 * (H_ * DH_);
        g_Ao[base0]     = __uint_as_float(f2tf32(o[nf][0] * inv0));
        g_Ao[base0 + 1] = __uint_as_float(f2tf32(o[nf][1] * inv0));
        g_Ao[base1]     = __uint_as_float(f2tf32(o[nf][2] * inv1));
        g_Ao[base1 + 1] = __uint_as_float(f2tf32(o[nf][3] * inv1));
    }
}

// ---------------- launch ----------------
extern "C" void kernel_launch(void* const* d_in, const int* in_sizes, int n_in,
                              void* d_out, int out_size) {
    const float* query = (const float*)d_in[0];
    const float* keyv  = (const float*)d_in[1];
    const float* W_QC  = (const float*)d_in[2];
    const float* W_KC  = (const float*)d_in[3];
    const float* W_QR  = (const float*)d_in[4];
    const float* W_KR  = (const float*)d_in[5];
    const float* W_V   = (const float*)d_in[6];
    const float* W_O   = (const float*)d_in[7];
    float* out = (float*)d_out;

    static float *pQf = nullptr, *pKf, *pVt, *pAo, *pAq, *pAkv;
    static float *pWqc, *pWkc, *pWqr, *pWkr, *pWv, *pWo;
    if (!pQf) {
        cudaFuncSetAttribute(gemm_tn, cudaFuncAttributeMaxDynamicSharedMemorySize, GEMM_SMEM);
        cudaFuncSetAttribute(flash_kernel, cudaFuncAttributeMaxDynamicSharedMemorySize, FLASH_SMEM);
        cudaGetSymbolAddress((void**)&pQf,  g_Qf);
        cudaGetSymbolAddress((void**)&pKf,  g_Kf);
        cudaGetSymbolAddress((void**)&pVt,  g_Vt);
        cudaGetSymbolAddress((void**)&pAo,  g_Ao);
        cudaGetSymbolAddress((void**)&pAq,  g_Aq);
        cudaGetSymbolAddress((void**)&pAkv, g_Akv);
        cudaGetSymbolAddress((void**)&pWqc, g_Wqc);
        cudaGetSymbolAddress((void**)&pWkc, g_Wkc);
        cudaGetSymbolAddress((void**)&pWqr, g_Wqr);
        cudaGetSymbolAddress((void**)&pWkr, g_Wkr);
        cudaGetSymbolAddress((void**)&pWv,  g_Wv);
        cudaGetSymbolAddress((void**)&pWo,  g_Wo);
    }

    rope_cache_kernel<<<256, 256>>>();

    // tf32 pre-rounding of all GEMM operands
    const int n4_act = B_ * M_ * D_ / 4;       // 2097152
    const int n4_w   = H_ * DH_ * D_ / 4;      // 1048576
    const int n4_wr  = H_ * DR_ * D_ / 4;      // 524288
    round_kernel<<<(n4_act + 255) / 256, 256>>>((const float4*)query, (float4*)pAq,  n4_act);
    round_kernel<<<(n4_act + 255) / 256, 256>>>((const float4*)keyv,  (float4*)pAkv, n4_act);
    round_kernel<<<(n4_w  + 255) / 256, 256>>>((const float4*)W_QC, (float4*)pWqc, n4_w);
    round_kernel<<<(n4_w  + 255) / 256, 256>>>((const float4*)W_KC, (float4*)pWkc, n4_w);
    round_kernel<<<(n4_wr + 255) / 256, 256>>>((const float4*)W_QR, (float4*)pWqr, n4_wr);
    round_kernel<<<(n4_wr + 255) / 256, 256>>>((const float4*)W_KR, (float4*)pWkr, n4_wr);
    round_kernel<<<(n4_w  + 255) / 256, 256>>>((const float4*)W_V,  (float4*)pWv,  n4_w);
    round_kernel<<<(n4_w  + 255) / 256, 256>>>((const float4*)W_O,  (float4*)pWo,  n4_w);

    dim3 thr(256);
    gemm_tn<<<dim3(16, 32), thr, GEMM_SMEM>>>(pAq,  pWqc, pQf, 0, 128, 192, 0);
    gemm_tn<<<dim3(8, 32),  thr, GEMM_SMEM>>>(pAq,  pWqr, pQf, 0, 64, 192, 128);
    gemm_tn<<<dim3(16, 32), thr, GEMM_SMEM>>>(pAkv, pWkc, pKf, 0, 128, 192, 0);
    gemm_tn<<<dim3(8, 32),  thr, GEMM_SMEM>>>(pAkv, pWkr, pKf, 0, 64, 192, 128);
    gemm_tn<<<dim3(16, 32), thr, GEMM_SMEM>>>(pAkv, pWv,  pAo, 0, 128, 128, 0);  // V staging
    transpose_v_kernel<<<dim3(4, 64, 32), dim3(32, 8)>>>();
    rope_apply_kernel<<<8192, 256>>>(pQf);
    rope_apply_kernel<<<8192, 256>>>(pKf);
    flash_kernel<<<dim3(32, 32), thr, FLASH_SMEM>>>();
    gemm_tn<<<dim3(16, 32), thr, GEMM_SMEM>>>(pAo, pWo, out, 1, 1, 0, 0);
}

// round 8
// speedup vs baseline: 1.8279x; 1.6198x over previous
#include <cuda_runtime.h>
#include <cuda_fp16.h>
#include <cstdint>
#include <math.h>

// Problem constants
#define B_   2
#define M_   2048
#define N_   2048
#define D_   2048
#define H_   16
#define DH_  128
#define DR_  64
#define DQK_ 192
#define SCALE_ 0.07216878364870323f  // 1/sqrt(192)

// ---------------- scratch (allocation-free: __device__ globals) ----------------
__device__ __half g_AqH [(size_t)B_ * M_ * D_];        // fp16 permuted-k query
__device__ __half g_AkvH[(size_t)B_ * N_ * D_];        // fp16 permuted-k key_value
__device__ __half g_WqcH[(size_t)H_ * DH_ * D_];
__device__ __half g_WkcH[(size_t)H_ * DH_ * D_];
__device__ __half g_WqrH[(size_t)H_ * DR_ * D_];
__device__ __half g_WkrH[(size_t)H_ * DR_ * D_];
__device__ __half g_WvH [(size_t)H_ * DH_ * D_];
__device__ __half g_WoH [(size_t)D_ * H_ * DH_];
__device__ __half g_QfH [(size_t)B_ * H_ * M_ * DQK_]; // (b,h,m,192) perm-d = [QC | roped QR]
__device__ __half g_KfH [(size_t)B_ * H_ * N_ * DQK_];
__device__ __half g_VpH [(size_t)B_ * H_ * N_ * DH_];  // V proj (b,h,n,d) unpermuted
__device__ __half g_VtH [(size_t)B_ * H_ * DH_ * N_];  // V transposed (b,h,d,n), n perm
__device__ __half g_AoH [(size_t)B_ * M_ * (H_ * DH_)];// attn out, perm-d
__device__ float g_cos[M_ * 32];
__device__ float g_sin[M_ * 32];

// ---------------- small PTX helpers ----------------
__device__ __forceinline__ void cp_async16h(__half* smem, const __half* gmem) {
    uint32_t s = (uint32_t)__cvta_generic_to_shared(smem);
    asm volatile("cp.async.cg.shared.global [%0], [%1], 16;\n" :: "r"(s), "l"(gmem) : "memory");
}
__device__ __forceinline__ void cp_commit() { asm volatile("cp.async.commit_group;\n" ::: "memory"); }
template <int N> __device__ __forceinline__ void cp_wait() {
    asm volatile("cp.async.wait_group %0;\n" :: "n"(N) : "memory");
}
__device__ __forceinline__ void mma_f16(float c[4],
        uint32_t a0, uint32_t a1, uint32_t a2, uint32_t a3,
        uint32_t b0, uint32_t b1) {
    asm volatile(
        "mma.sync.aligned.m16n8k16.row.col.f32.f16.f16.f32 "
        "{%0,%1,%2,%3},{%4,%5,%6,%7},{%8,%9},{%0,%1,%2,%3};\n"
        : "+f"(c[0]), "+f"(c[1]), "+f"(c[2]), "+f"(c[3])
        : "r"(a0), "r"(a1), "r"(a2), "r"(a3), "r"(b0), "r"(b1));
}
__device__ __forceinline__ uint32_t h2u(__half2 h) { return *(uint32_t*)&h; }
// permuted position of k within its 32-block (pairs stay adjacent)
__device__ __forceinline__ int posk(int k) {
    return ((k >> 1) & 3) * 8 + ((k >> 3) & 3) * 2 + (k & 1);
}

// ---------------- fp32 -> fp16 convert with 32-block k-permutation ----------------
// permuted pos 8t+j holds k: j=0,1->2t,2t+1 ; j=2,3->2t+8,2t+9 ; j=4..7 -> +16,+24
__global__ void conv_perm_kernel(const float4* __restrict__ src, uint4* __restrict__ dst, int nblk) {
    int i = blockIdx.x * blockDim.x + threadIdx.x;
    if (i >= nblk) return;
    float v[32];
    const float4* s = src + (size_t)i * 8;
#pragma unroll
    for (int j = 0; j < 8; ++j) {
        float4 f = s[j];
        v[4*j] = f.x; v[4*j+1] = f.y; v[4*j+2] = f.z; v[4*j+3] = f.w;
    }
    uint4* d = dst + (size_t)i * 4;
#pragma unroll
    for (int t = 0; t < 4; ++t) {
        uint32_t h[4];
#pragma unroll
        for (int jj = 0; jj < 4; ++jj) {
            int k = 2 * t + 8 * jj;
            h[jj] = h2u(__floats2half2_rn(v[k], v[k + 1]));
        }
        d[t] = make_uint4(h[0], h[1], h[2], h[3]);
    }
}

// ---------------- RoPE cache + apply (on permuted fp16 layout) ----------------
__global__ void rope_cache_kernel() {
    int idx = blockIdx.x * blockDim.x + threadIdx.x;
    if (idx >= M_ * 32) return;
    int s = idx >> 5, i = idx & 31;
    double e = (double)(2 * i) / 64.0;
    float freq = (float)(1.0 / pow(1000000.0, e));
    float ang = (float)s * freq;
    double a = (double)ang;
    g_cos[idx] = (float)cos(a);
    g_sin[idx] = (float)sin(a);
}

__global__ void rope_apply_h(__half* __restrict__ buf) {
    int idx = blockIdx.x * blockDim.x + threadIdx.x;
    if (idx >= B_ * H_ * M_ * 32) return;
    int i5 = idx & 31;
    int s = (idx >> 5) & (M_ - 1);
    int bh = idx >> 16;
    int blk = i5 >> 4, pp = i5 & 15;
    int q = (pp >> 2) + ((pp & 3) << 2);          // k-pair index of this permuted pair
    int fi = blk * 16 + q;
    size_t base = ((size_t)bh * M_ + s) * DQK_ + DH_ + blk * 32 + 2 * pp;
    float c = g_cos[(s << 5) + fi], sn = g_sin[(s << 5) + fi];
    __half2 xv = *(__half2*)(buf + base);
    float x0 = __low2float(xv), x1 = __high2float(xv);
    *(__half2*)(buf + base) = __floats2half2_rn(x0 * c - x1 * sn, x1 * c + x0 * sn);
}

// ---------------- V transpose: (b,h,n,d) -> (b,h,d,n) with n permuted ----------------
__global__ void transpose_v_kernel() {
    __shared__ __half ts[32][33];
    int bh = blockIdx.z;
    int d0 = blockIdx.x * 32, n0 = blockIdx.y * 32;
    const __half* src = g_VpH + (size_t)bh * N_ * DH_;
    __half* dst = g_VtH + (size_t)bh * DH_ * N_;
    int tx = threadIdx.x, ty = threadIdx.y;
#pragma unroll
    for (int i = 0; i < 32; i += 8)
        ts[ty + i][tx] = src[(size_t)(n0 + ty + i) * DH_ + d0 + tx];
    __syncthreads();
    int pn = posk(tx);
#pragma unroll
    for (int i = 0; i < 32; i += 8)
        dst[(size_t)(d0 + ty + i) * N_ + n0 + pn] = ts[tx][ty + i];
}

// ---------------- fp16 GEMM: C = A @ W^T, tile 128x128x32, 4-stage ----------------
#define G_ASZ (128 * 32)                        // halves per stage per operand
#define G_STG 4
#define GEMM_SMEM (G_STG * 2 * G_ASZ * 2)       // 65536 B

__global__ __launch_bounds__(256, 2)
void gemm_h(const __half* __restrict__ A, const __half* __restrict__ W,
            void* __restrict__ Cout, int mode, int dh, int ld, int off) {
    extern __shared__ __half smh[];
    __half* smA = smh;
    __half* smB = smh + G_STG * G_ASZ;

    const int tid = threadIdx.x;
    const int m0 = blockIdx.y * 128;
    const int n0 = blockIdx.x * 128;
    const __half* Ab = A + (size_t)m0 * D_;
    const __half* Wb = W + (size_t)n0 * D_;

    auto load_stage = [&](int kt, int s) {
        const int k0 = kt * 32;
        __half* sa = smA + s * G_ASZ;
        __half* sb = smB + s * G_ASZ;
#pragma unroll
        for (int i = 0; i < 2; ++i) {
            int c = tid + i * 256;
            int row = c >> 2, t4 = c & 3;
            cp_async16h(sa + row * 32 + t4 * 8, Ab + (size_t)row * D_ + k0 + t4 * 8);
        }
#pragma unroll
        for (int i = 0; i < 2; ++i) {
            int c = tid + i * 256;
            int row = c >> 2, t4 = c & 3;
            cp_async16h(sb + row * 32 + t4 * 8, Wb + (size_t)row * D_ + k0 + t4 * 8);
        }
        cp_commit();
    };

    float acc[4][4][4] = {};
    const int warp = tid >> 5, lane = tid & 31;
    const int wm = warp >> 2, wn = warp & 3;   // 2x4 warps, warp tile 64x32
    const int g = lane >> 2, t = lane & 3;

    load_stage(0, 0); load_stage(1, 1); load_stage(2, 2);
    const int NKT = D_ / 32;  // 64
    for (int kt = 0; kt < NKT; ++kt) {
        int cur = kt & 3;
        if (kt + 3 < NKT)      { load_stage(kt + 3, (kt + 3) & 3); cp_wait<3>(); }
        else if (kt + 2 < NKT) cp_wait<2>();
        else if (kt + 1 < NKT) cp_wait<1>();
        else                   cp_wait<0>();
        __syncthreads();
        const uint4* sa = (const uint4*)(smA + cur * G_ASZ);
        const uint4* sb = (const uint4*)(smB + cur * G_ASZ);
        uint4 af[4][2];
#pragma unroll
        for (int im = 0; im < 4; ++im) {
            int r = wm * 64 + im * 16 + g;
            af[im][0] = sa[r * 4 + t];
            af[im][1] = sa[(r + 8) * 4 + t];
        }
#pragma unroll
        for (int in = 0; in < 4; ++in) {
            uint4 bq = sb[(wn * 32 + in * 8 + g) * 4 + t];
#pragma unroll
            for (int im = 0; im < 4; ++im) {
                mma_f16(acc[im][in], af[im][0].x, af[im][1].x, af[im][0].y, af[im][1].y, bq.x, bq.y);
                mma_f16(acc[im][in], af[im][0].z, af[im][1].z, af[im][0].w, af[im][1].w, bq.z, bq.w);
            }
        }
        __syncthreads();
    }

#pragma unroll
    for (int im = 0; im < 4; ++im) {
        int r0g = m0 + wm * 64 + im * 16 + g;
#pragma unroll
        for (int in = 0; in < 4; ++in) {
            int c0 = n0 + wn * 32 + in * 8 + 2 * t;
            if (mode == 2) {
                float* C = (float*)Cout;
                *(float2*)&C[(size_t)r0g * 2048 + c0] =
                    make_float2(acc[im][in][0], acc[im][in][1]);
                *(float2*)&C[(size_t)(r0g + 8) * 2048 + c0] =
                    make_float2(acc[im][in][2], acc[im][in][3]);
            } else {
                __half* C = (__half*)Cout;
                int b = r0g >> 11, m = r0g & (M_ - 1);
                int h = c0 / dh, d = c0 - h * dh;
                int dcol = (mode == 0) ? ((d & ~31) + posk(d & 31)) : d;
                size_t base = (((size_t)(b * H_ + h) * M_) + m) * ld + off + dcol;
                *(__half2*)&C[base] = __floats2half2_rn(acc[im][in][0], acc[im][in][1]);
                *(__half2*)&C[base + (size_t)8 * ld] = __floats2half2_rn(acc[im][in][2], acc[im][in][3]);
            }
        }
    }
}

// ---------------- fused flash attention fp16 (Br=Bc=64, d=192, dv=128) ----------------
// halves: Q 64x192 | K 2x 64x192 | V 128x72 | P 64x64 ; misc floats after
#define FL_KS 12288
#define FL_VS 36864
#define FL_PS 46080
#define FL_TOTH 50176
#define FLASH_SMEM (FL_TOTH * 2 + 448 * 4)   // 102144 B

__global__ __launch_bounds__(256, 2)
void flash_kernel() {
    extern __shared__ __half smh[];
    __half* Qs = smh;
    __half* Ks = smh + FL_KS;
    __half* Vs = smh + FL_VS;
    __half* Ps = smh + FL_PS;
    float* row_m  = (float*)(smh + FL_TOTH);
    float* row_l  = row_m + 64;
    float* row_sc = row_l + 64;
    float* red    = row_sc + 64;    // 64 x 2
    float* red2   = red + 128;      // 64 x 2

    const int tid = threadIdx.x;
    const int m0 = blockIdx.x * 64;
    const int bh = blockIdx.y;
    const int b = bh >> 4, h = bh & 15;

    const __half* Qg = g_QfH + ((size_t)bh * M_ + m0) * DQK_;
    const __half* Kg = g_KfH + (size_t)bh * N_ * DQK_;
    const __half* Vg = g_VtH + (size_t)bh * DH_ * N_;

    auto load_K = [&](int j, int buf) {
        const __half* src = Kg + (size_t)j * 64 * DQK_;
        __half* dst = Ks + buf * 12288;
#pragma unroll
        for (int i = 0; i < 6; ++i) {
            int c = tid + i * 256;
            cp_async16h(dst + c * 8, src + c * 8);
        }
        cp_commit();
    };
    auto load_V = [&](int j) {
#pragma unroll
        for (int i = 0; i < 4; ++i) {
            int c = tid + i * 256;
            int row = c >> 3, cc = c & 7;
            cp_async16h(Vs + row * 72 + cc * 8, Vg + (size_t)row * N_ + j * 64 + cc * 8);
        }
        cp_commit();
    };

#pragma unroll
    for (int i = 0; i < 6; ++i) {
        int c = tid + i * 256;
        cp_async16h(Qs + c * 8, Qg + c * 8);
    }
    cp_commit();
    load_K(0, 0);
    load_V(0);
    if (tid < 64) { row_m[tid] = -1e30f; row_l[tid] = 0.f; }

    float o[8][4] = {};
    const int warp = tid >> 5, lane = tid & 31;
    const int wm = warp >> 1, wn = warp & 1;   // S: 4x2 warps (16x32); PV: 16x64
    const int g = lane >> 2, t = lane & 3;
    const int r0 = wm * 16 + g;
    const uint4* Qs4 = (const uint4*)Qs;
    const uint4* Vs4 = (const uint4*)Vs;
    uint4* Ps4 = (uint4*)Ps;

    for (int j = 0; j < N_ / 64; ++j) {
        const int cur = j & 1;
        const bool more = (j + 1 < N_ / 64);
        if (more) { load_K(j + 1, cur ^ 1); cp_wait<2>(); }
        else      { cp_wait<1>(); }
        __syncthreads();
        const uint4* Ks4 = (const uint4*)(Ks + cur * 12288);

        // ---- S = Q K^T (6 blocks of 32-k) ----
        float s[4][4] = {};
#pragma unroll
        for (int blk = 0; blk < 6; ++blk) {
            int c = blk * 4 + t;
            uint4 q0 = Qs4[r0 * 24 + c];
            uint4 q1 = Qs4[(r0 + 8) * 24 + c];
#pragma unroll
            for (int nf = 0; nf < 4; ++nf) {
                uint4 kq = Ks4[(wn * 32 + nf * 8 + g) * 24 + c];
                mma_f16(s[nf], q0.x, q1.x, q0.y, q1.y, kq.x, kq.y);
                mma_f16(s[nf], q0.z, q1.z, q0.w, q1.w, kq.z, kq.w);
            }
        }

        // ---- online softmax ----
        float mx0 = -1e30f, mx1 = -1e30f;
#pragma unroll
        for (int nf = 0; nf < 4; ++nf) {
            s[nf][0] *= SCALE_; s[nf][1] *= SCALE_; s[nf][2] *= SCALE_; s[nf][3] *= SCALE_;
            mx0 = fmaxf(mx0, fmaxf(s[nf][0], s[nf][1]));
            mx1 = fmaxf(mx1, fmaxf(s[nf][2], s[nf][3]));
        }
        mx0 = fmaxf(mx0, __shfl_xor_sync(0xffffffffu, mx0, 1));
        mx0 = fmaxf(mx0, __shfl_xor_sync(0xffffffffu, mx0, 2));
        mx1 = fmaxf(mx1, __shfl_xor_sync(0xffffffffu, mx1, 1));
        mx1 = fmaxf(mx1, __shfl_xor_sync(0xffffffffu, mx1, 2));
        if (t == 0) { red[r0 * 2 + wn] = mx0; red[(r0 + 8) * 2 + wn] = mx1; }
        __syncthreads();
        if (tid < 64) {
            float nm = fmaxf(row_m[tid], fmaxf(red[2 * tid], red[2 * tid + 1]));
            row_sc[tid] = __expf(row_m[tid] - nm);
            row_m[tid] = nm;
        }
        __syncthreads();
        float m0r = row_m[r0], m1r = row_m[r0 + 8];
        float sum0 = 0.f, sum1 = 0.f;
        uint32_t ph0[4], ph1[4];
#pragma unroll
        for (int nf = 0; nf < 4; ++nf) {
            float p0 = __expf(s[nf][0] - m0r), p1 = __expf(s[nf][1] - m0r);
            float p2 = __expf(s[nf][2] - m1r), p3 = __expf(s[nf][3] - m1r);
            sum0 += p0 + p1; sum1 += p2 + p3;
            ph0[nf] = h2u(__floats2half2_rn(p0, p1));
            ph1[nf] = h2u(__floats2half2_rn(p2, p3));
        }
        // P rows: chunk (wn*4 + t) holds permuted positions 8t+2nf within wn's 32-block
        Ps4[r0 * 8 + wn * 4 + t]       = make_uint4(ph0[0], ph0[1], ph0[2], ph0[3]);
        Ps4[(r0 + 8) * 8 + wn * 4 + t] = make_uint4(ph1[0], ph1[1], ph1[2], ph1[3]);
        sum0 += __shfl_xor_sync(0xffffffffu, sum0, 1);
        sum0 += __shfl_xor_sync(0xffffffffu, sum0, 2);
        sum1 += __shfl_xor_sync(0xffffffffu, sum1, 1);
        sum1 += __shfl_xor_sync(0xffffffffu, sum1, 2);
        if (t == 0) { red2[r0 * 2 + wn] = sum0; red2[(r0 + 8) * 2 + wn] = sum1; }
        float sc0 = row_sc[r0], sc1 = row_sc[r0 + 8];
#pragma unroll
        for (int nf = 0; nf < 8; ++nf) {
            o[nf][0] *= sc0; o[nf][1] *= sc0; o[nf][2] *= sc1; o[nf][3] *= sc1;
        }
        if (more) cp_wait<1>(); else cp_wait<0>();   // V(j) done (K(j+1) may fly)
        __syncthreads();
        if (tid < 64)
            row_l[tid] = row_l[tid] * row_sc[tid] + red2[2 * tid] + red2[2 * tid + 1];

        // ---- O += P @ V (2 blocks of 32-kv; warp tile 16x64 d) ----
#pragma unroll
        for (int blk = 0; blk < 2; ++blk) {
            int c = blk * 4 + t;
            uint4 p0 = Ps4[r0 * 8 + c];
            uint4 p1 = Ps4[(r0 + 8) * 8 + c];
#pragma unroll
            for (int nf = 0; nf < 8; ++nf) {
                uint4 vq = Vs4[(wn * 64 + nf * 8 + g) * 9 + c];
                mma_f16(o[nf], p0.x, p1.x, p0.y, p1.y, vq.x, vq.y);
                mma_f16(o[nf], p0.z, p1.z, p0.w, p1.w, vq.z, vq.w);
            }
        }
        __syncthreads();
        if (more) load_V(j + 1);
    }

    float inv0 = 1.f / row_l[r0];
    float inv1 = 1.f / row_l[r0 + 8];
#pragma unroll
    for (int nf = 0; nf < 8; ++nf) {
        int cpos = h * 128 + wn * 64 + (nf >> 2) * 32 + 8 * t + 2 * (nf & 3);
        size_t base0 = ((size_t)(b * M_) + m0 + r0) * 2048 + cpos;
        *(__half2*)&g_AoH[base0] = __floats2half2_rn(o[nf][0] * inv0, o[nf][1] * inv0);
        *(__half2*)&g_AoH[base0 + (size_t)8 * 2048] =
            __floats2half2_rn(o[nf][2] * inv1, o[nf][3] * inv1);
    }
}

// ---------------- launch ----------------
extern "C" void kernel_launch(void* const* d_in, const int* in_sizes, int n_in,
                              void* d_out, int out_size) {
    const float* query = (const float*)d_in[0];
    const float* keyv  = (const float*)d_in[1];
    const float* W_QC  = (const float*)d_in[2];
    const float* W_KC  = (const float*)d_in[3];
    const float* W_QR  = (const float*)d_in[4];
    const float* W_KR  = (const float*)d_in[5];
    const float* W_V   = (const float*)d_in[6];
    const float* W_O   = (const float*)d_in[7];
    float* out = (float*)d_out;

    static __half *pAq = nullptr, *pAkv, *pWqc, *pWkc, *pWqr, *pWkr, *pWv, *pWo;
    static __half *pQf, *pKf, *pVp, *pVt, *pAo;
    if (!pAq) {
        cudaFuncSetAttribute(gemm_h, cudaFuncAttributeMaxDynamicSharedMemorySize, GEMM_SMEM);
        cudaFuncSetAttribute(flash_kernel, cudaFuncAttributeMaxDynamicSharedMemorySize, FLASH_SMEM);
        cudaGetSymbolAddress((void**)&pAq,  g_AqH);
        cudaGetSymbolAddress((void**)&pAkv, g_AkvH);
        cudaGetSymbolAddress((void**)&pWqc, g_WqcH);
        cudaGetSymbolAddress((void**)&pWkc, g_WkcH);
        cudaGetSymbolAddress((void**)&pWqr, g_WqrH);
        cudaGetSymbolAddress((void**)&pWkr, g_WkrH);
        cudaGetSymbolAddress((void**)&pWv,  g_WvH);
        cudaGetSymbolAddress((void**)&pWo,  g_WoH);
        cudaGetSymbolAddress((void**)&pQf,  g_QfH);
        cudaGetSymbolAddress((void**)&pKf,  g_KfH);
        cudaGetSymbolAddress((void**)&pVp,  g_VpH);
        cudaGetSymbolAddress((void**)&pVt,  g_VtH);
        cudaGetSymbolAddress((void**)&pAo,  g_AoH);
    }

    rope_cache_kernel<<<256, 256>>>();

    // fp32 -> fp16 with 32-block k permutation
    const int nb_act = B_ * M_ * D_ / 32;     // 262144
    const int nb_w   = H_ * DH_ * D_ / 32;    // 131072
    const int nb_wr  = H_ * DR_ * D_ / 32;    // 65536
    conv_perm_kernel<<<nb_act / 256, 256>>>((const float4*)query, (uint4*)pAq,  nb_act);
    conv_perm_kernel<<<nb_act / 256, 256>>>((const float4*)keyv,  (uint4*)pAkv, nb_act);
    conv_perm_kernel<<<nb_w  / 256, 256>>>((const float4*)W_QC, (uint4*)pWqc, nb_w);
    conv_perm_kernel<<<nb_w  / 256, 256>>>((const float4*)W_KC, (uint4*)pWkc, nb_w);
    conv_perm_kernel<<<nb_wr / 256, 256>>>((const float4*)W_QR, (uint4*)pWqr, nb_wr);
    conv_perm_kernel<<<nb_wr / 256, 256>>>((const float4*)W_KR, (uint4*)pWkr, nb_wr);
    conv_perm_kernel<<<nb_w  / 256, 256>>>((const float4*)W_V,  (uint4*)pWv,  nb_w);
    conv_perm_kernel<<<nb_w  / 256, 256>>>((const float4*)W_O,  (uint4*)pWo,  nb_w);

    dim3 thr(256);
    gemm_h<<<dim3(16, 32), thr, GEMM_SMEM>>>(pAq,  pWqc, pQf, 0, 128, 192, 0);
    gemm_h<<<dim3(8, 32),  thr, GEMM_SMEM>>>(pAq,  pWqr, pQf, 0, 64, 192, 128);
    gemm_h<<<dim3(16, 32), thr, GEMM_SMEM>>>(pAkv, pWkc, pKf, 0, 128, 192, 0);
    gemm_h<<<dim3(8, 32),  thr, GEMM_SMEM>>>(pAkv, pWkr, pKf, 0, 64, 192, 128);
    gemm_h<<<dim3(16, 32), thr, GEMM_SMEM>>>(pAkv, pWv,  pVp, 1, 128, 128, 0);
    transpose_v_kernel<<<dim3(4, 64, 32), dim3(32, 8)>>>();
    rope_apply_h<<<8192, 256>>>(pQf);
    rope_apply_h<<<8192, 256>>>(pKf);
    flash_kernel<<<dim3(32, 32), thr, FLASH_SMEM>>>();
    gemm_h<<<dim3(16, 32), thr, GEMM_SMEM>>>(pAo, pWo, out, 2, 1, 2048, 0);
}

// round 10
// speedup vs baseline: 2.1612x; 1.1824x over previous
#include <cuda_runtime.h>
#include <cuda_fp16.h>
#include <cstdint>
#include <math.h>

// Problem constants
#define B_   2
#define M_   2048
#define N_   2048
#define D_   2048
#define H_   16
#define DH_  128
#define DR_  64
#define DQK_ 192
#define SCALE_ 0.07216878364870323f  // 1/sqrt(192)

// ---------------- scratch (allocation-free: __device__ globals) ----------------
__device__ __half g_AqH [(size_t)B_ * M_ * D_];        // fp16 permuted-k query
__device__ __half g_AkvH[(size_t)B_ * N_ * D_];        // fp16 permuted-k key_value
__device__ __half g_WqcH[(size_t)H_ * DH_ * D_];
__device__ __half g_WkcH[(size_t)H_ * DH_ * D_];
__device__ __half g_WqrH[(size_t)H_ * DR_ * D_];
__device__ __half g_WkrH[(size_t)H_ * DR_ * D_];
__device__ __half g_WvH [(size_t)H_ * DH_ * D_];
__device__ __half g_WoH [(size_t)D_ * H_ * DH_];
__device__ __half g_QfH [(size_t)B_ * H_ * M_ * DQK_]; // (b,h,m,192) perm-d, pre-scaled
__device__ __half g_KfH [(size_t)B_ * H_ * N_ * DQK_];
__device__ __half g_VpH [(size_t)B_ * H_ * N_ * DH_];  // V proj (b,h,n,d) unpermuted
__device__ __half g_VtH [(size_t)B_ * H_ * DH_ * N_];  // V transposed (b,h,d,n), n perm
__device__ __half g_AoH [(size_t)B_ * M_ * (H_ * DH_)];// attn out, perm-d
__device__ float g_cos[M_ * 32];
__device__ float g_sin[M_ * 32];

// ---------------- small PTX helpers ----------------
__device__ __forceinline__ void cp_async16h(__half* smem, const __half* gmem) {
    uint32_t s = (uint32_t)__cvta_generic_to_shared(smem);
    asm volatile("cp.async.cg.shared.global [%0], [%1], 16;\n" :: "r"(s), "l"(gmem) : "memory");
}
__device__ __forceinline__ void cp_commit() { asm volatile("cp.async.commit_group;\n" ::: "memory"); }
template <int N> __device__ __forceinline__ void cp_wait() {
    asm volatile("cp.async.wait_group %0;\n" :: "n"(N) : "memory");
}
__device__ __forceinline__ void mma_f16(float c[4],
        uint32_t a0, uint32_t a1, uint32_t a2, uint32_t a3,
        uint32_t b0, uint32_t b1) {
    asm volatile(
        "mma.sync.aligned.m16n8k16.row.col.f32.f16.f16.f32 "
        "{%0,%1,%2,%3},{%4,%5,%6,%7},{%8,%9},{%0,%1,%2,%3};\n"
        : "+f"(c[0]), "+f"(c[1]), "+f"(c[2]), "+f"(c[3])
        : "r"(a0), "r"(a1), "r"(a2), "r"(a3), "r"(b0), "r"(b1));
}
__device__ __forceinline__ uint32_t h2u(__half2 h) { return *(uint32_t*)&h; }
// permuted position of k within its 32-block (pairs stay adjacent)
__device__ __forceinline__ int posk(int k) {
    return ((k >> 1) & 3) * 8 + ((k >> 3) & 3) * 2 + (k & 1);
}

// ---------------- fp32 -> fp16 convert with 32-block k-permutation ----------------
__global__ void conv_perm_kernel(const float4* __restrict__ src, uint4* __restrict__ dst, int nblk) {
    int i = blockIdx.x * blockDim.x + threadIdx.x;
    if (i >= nblk) return;
    float v[32];
    const float4* s = src + (size_t)i * 8;
#pragma unroll
    for (int j = 0; j < 8; ++j) {
        float4 f = s[j];
        v[4*j] = f.x; v[4*j+1] = f.y; v[4*j+2] = f.z; v[4*j+3] = f.w;
    }
    uint4* d = dst + (size_t)i * 4;
#pragma unroll
    for (int t = 0; t < 4; ++t) {
        uint32_t h[4];
#pragma unroll
        for (int jj = 0; jj < 4; ++jj) {
            int k = 2 * t + 8 * jj;
            h[jj] = h2u(__floats2half2_rn(v[k], v[k + 1]));
        }
        d[t] = make_uint4(h[0], h[1], h[2], h[3]);
    }
}

// ---------------- RoPE cache + apply (on permuted fp16 layout) ----------------
__global__ void rope_cache_kernel() {
    int idx = blockIdx.x * blockDim.x + threadIdx.x;
    if (idx >= M_ * 32) return;
    int s = idx >> 5, i = idx & 31;
    double e = (double)(2 * i) / 64.0;
    float freq = (float)(1.0 / pow(1000000.0, e));
    float ang = (float)s * freq;
    double a = (double)ang;
    g_cos[idx] = (float)cos(a);
    g_sin[idx] = (float)sin(a);
}

__global__ void rope_apply_h(__half* __restrict__ buf) {
    int idx = blockIdx.x * blockDim.x + threadIdx.x;
    if (idx >= B_ * H_ * M_ * 32) return;
    int i5 = idx & 31;
    int s = (idx >> 5) & (M_ - 1);
    int bh = idx >> 16;
    int blk = i5 >> 4, pp = i5 & 15;
    int q = (pp >> 2) + ((pp & 3) << 2);
    int fi = blk * 16 + q;
    size_t base = ((size_t)bh * M_ + s) * DQK_ + DH_ + blk * 32 + 2 * pp;
    float c = g_cos[(s << 5) + fi], sn = g_sin[(s << 5) + fi];
    __half2 xv = *(__half2*)(buf + base);
    float x0 = __low2float(xv), x1 = __high2float(xv);
    *(__half2*)(buf + base) = __floats2half2_rn(x0 * c - x1 * sn, x1 * c + x0 * sn);
}

// ---------------- V transpose: (b,h,n,d) -> (b,h,d,n) with n permuted ----------------
__global__ void transpose_v_kernel() {
    __shared__ __half ts[32][33];
    int bh = blockIdx.z;
    int d0 = blockIdx.x * 32, n0 = blockIdx.y * 32;
    const __half* src = g_VpH + (size_t)bh * N_ * DH_;
    __half* dst = g_VtH + (size_t)bh * DH_ * N_;
    int tx = threadIdx.x, ty = threadIdx.y;
#pragma unroll
    for (int i = 0; i < 32; i += 8)
        ts[ty + i][tx] = src[(size_t)(n0 + ty + i) * DH_ + d0 + tx];
    __syncthreads();
    int pn = posk(tx);
#pragma unroll
    for (int i = 0; i < 32; i += 8)
        dst[(size_t)(d0 + ty + i) * N_ + n0 + pn] = ts[tx][ty + i];
}

// ---------------- fp16 GEMM: C = A @ W^T, tile 128x128x32, 4-stage ----------------
#define G_ASZ (128 * 32)
#define G_STG 4
#define GEMM_SMEM (G_STG * 2 * G_ASZ * 2)       // 65536 B

__global__ __launch_bounds__(256, 2)
void gemm_h(const __half* __restrict__ A, const __half* __restrict__ W,
            void* __restrict__ Cout, int mode, int dh, int ld, int off, float es) {
    extern __shared__ __half smh[];
    __half* smA = smh;
    __half* smB = smh + G_STG * G_ASZ;

    const int tid = threadIdx.x;
    const int m0 = blockIdx.y * 128;
    const int n0 = blockIdx.x * 128;
    const __half* Ab = A + (size_t)m0 * D_;
    const __half* Wb = W + (size_t)n0 * D_;

    auto load_stage = [&](int kt, int s) {
        const int k0 = kt * 32;
        __half* sa = smA + s * G_ASZ;
        __half* sb = smB + s * G_ASZ;
#pragma unroll
        for (int i = 0; i < 2; ++i) {
            int c = tid + i * 256;
            int row = c >> 2, t4 = c & 3;
            cp_async16h(sa + row * 32 + t4 * 8, Ab + (size_t)row * D_ + k0 + t4 * 8);
        }
#pragma unroll
        for (int i = 0; i < 2; ++i) {
            int c = tid + i * 256;
            int row = c >> 2, t4 = c & 3;
            cp_async16h(sb + row * 32 + t4 * 8, Wb + (size_t)row * D_ + k0 + t4 * 8);
        }
        cp_commit();
    };

    float acc[4][4][4] = {};
    const int warp = tid >> 5, lane = tid & 31;
    const int wm = warp >> 2, wn = warp & 3;
    const int g = lane >> 2, t = lane & 3;

    load_stage(0, 0); load_stage(1, 1); load_stage(2, 2);
    const int NKT = D_ / 32;
    for (int kt = 0; kt < NKT; ++kt) {
        int cur = kt & 3;
        if (kt + 3 < NKT)      { load_stage(kt + 3, (kt + 3) & 3); cp_wait<3>(); }
        else if (kt + 2 < NKT) cp_wait<2>();
        else if (kt + 1 < NKT) cp_wait<1>();
        else                   cp_wait<0>();
        __syncthreads();
        const uint4* sa = (const uint4*)(smA + cur * G_ASZ);
        const uint4* sb = (const uint4*)(smB + cur * G_ASZ);
        uint4 af[4][2];
#pragma unroll
        for (int im = 0; im < 4; ++im) {
            int r = wm * 64 + im * 16 + g;
            af[im][0] = sa[r * 4 + t];
            af[im][1] = sa[(r + 8) * 4 + t];
        }
#pragma unroll
        for (int in = 0; in < 4; ++in) {
            uint4 bq = sb[(wn * 32 + in * 8 + g) * 4 + t];
#pragma unroll
            for (int im = 0; im < 4; ++im) {
                mma_f16(acc[im][in], af[im][0].x, af[im][1].x, af[im][0].y, af[im][1].y, bq.x, bq.y);
                mma_f16(acc[im][in], af[im][0].z, af[im][1].z, af[im][0].w, af[im][1].w, bq.z, bq.w);
            }
        }
        __syncthreads();
    }

#pragma unroll
    for (int im = 0; im < 4; ++im) {
        int r0g = m0 + wm * 64 + im * 16 + g;
#pragma unroll
        for (int in = 0; in < 4; ++in) {
            int c0 = n0 + wn * 32 + in * 8 + 2 * t;
            if (mode == 2) {
                float* C = (float*)Cout;
                *(float2*)&C[(size_t)r0g * 2048 + c0] =
                    make_float2(acc[im][in][0], acc[im][in][1]);
                *(float2*)&C[(size_t)(r0g + 8) * 2048 + c0] =
                    make_float2(acc[im][in][2], acc[im][in][3]);
            } else {
                __half* C = (__half*)Cout;
                int b = r0g >> 11, m = r0g & (M_ - 1);
                int h = c0 / dh, d = c0 - h * dh;
                int dcol = (mode == 0) ? ((d & ~31) + posk(d & 31)) : d;
                size_t base = (((size_t)(b * H_ + h) * M_) + m) * ld + off + dcol;
                *(__half2*)&C[base] = __floats2half2_rn(acc[im][in][0] * es, acc[im][in][1] * es);
                *(__half2*)&C[base + (size_t)8 * ld] =
                    __floats2half2_rn(acc[im][in][2] * es, acc[im][in][3] * es);
            }
        }
    }
}

// ---------------- fused flash attention fp16 (Br=128, Bc=64, d=192, dv=128) ----------------
// halves: Q 128x192 | K 2x 64x192 | V 2x 128x64  -> 65536 halves = 131072 B
#define FL_KOFF 24576
#define FL_VOFF 49152
#define FLASH_SMEM (65536 * 2)

__global__ __launch_bounds__(256, 1)
void flash_kernel() {
    extern __shared__ __half smh[];
    __half* Qs = smh;
    __half* Ks = smh + FL_KOFF;
    __half* Vs = smh + FL_VOFF;

    const int tid = threadIdx.x;
    const int m0 = blockIdx.x * 128;
    const int bh = blockIdx.y;
    const int b = bh >> 4, h = bh & 15;

    const __half* Qg = g_QfH + ((size_t)bh * M_ + m0) * DQK_;
    const __half* Kg = g_KfH + (size_t)bh * N_ * DQK_;
    const __half* Vg = g_VtH + (size_t)bh * DH_ * N_;

    // Q: 128x192, swizzled chunks (cc ^ ((row&1)<<2))
#pragma unroll
    for (int i = 0; i < 12; ++i) {
        int c = tid + i * 256;
        int row = c / 24, cc = c % 24;
        int phys = cc ^ ((row & 1) << 2);
        cp_async16h(Qs + row * 192 + phys * 8, Qg + (size_t)row * 192 + cc * 8);
    }
    cp_commit();

    auto load_K = [&](int j, int buf) {
        const __half* src = Kg + (size_t)j * 64 * DQK_;
        __half* dst = Ks + buf * 12288;
#pragma unroll
        for (int i = 0; i < 6; ++i) {
            int c = tid + i * 256;
            int row = c / 24, cc = c % 24;
            int phys = cc ^ ((row & 1) << 2);
            cp_async16h(dst + row * 192 + phys * 8, src + (size_t)row * 192 + cc * 8);
        }
        cp_commit();
    };
    auto load_V = [&](int j, int buf) {
        __half* dst = Vs + buf * 8192;
#pragma unroll
        for (int i = 0; i < 4; ++i) {
            int c = tid + i * 256;
            int row = c >> 3, cc = c & 7;
            int phys = cc ^ ((row & 1) << 2);
            cp_async16h(dst + row * 64 + phys * 8, Vg + (size_t)row * N_ + j * 64 + cc * 8);
        }
        cp_commit();
    };

    load_K(0, 0);
    load_V(0, 0);

    const int warp = tid >> 5, lane = tid & 31;
    const int g = lane >> 2, t = lane & 3;
    const int r0 = warp * 16 + g;          // warp owns rows r0, r0+8 (16 rows total)
    const int swz = (g & 1) << 2;
    const int qr0 = r0 * 24, qr1 = (r0 + 8) * 24;

    float o[16][4] = {};
    float m0r = -1e30f, m1r = -1e30f, l0 = 0.f, l1 = 0.f;

    for (int j = 0; j < N_ / 64; ++j) {
        cp_wait<0>();
        __syncthreads();
        if (j + 1 < N_ / 64) { load_K(j + 1, (j + 1) & 1); load_V(j + 1, (j + 1) & 1); }

        const uint4* Ks4 = (const uint4*)(Ks + (j & 1) * 12288);
        const uint4* Vs4 = (const uint4*)(Vs + (j & 1) * 8192);
        const uint4* Qs4 = (const uint4*)Qs;

        // ---- S = Q K^T : warp tile 16x64, 6 k-blocks of 32 ----
        float s[8][4] = {};
#pragma unroll
        for (int blk = 0; blk < 6; ++blk) {
            int c = (blk * 4 + t) ^ swz;
            uint4 q0 = Qs4[qr0 + c];
            uint4 q1 = Qs4[qr1 + c];
#pragma unroll
            for (int nf = 0; nf < 8; ++nf) {
                uint4 kq = Ks4[(nf * 8 + g) * 24 + c];
                mma_f16(s[nf], q0.x, q1.x, q0.y, q1.y, kq.x, kq.y);
                mma_f16(s[nf], q0.z, q1.z, q0.w, q1.w, kq.z, kq.w);
            }
        }

        // ---- warp-local online softmax (Q pre-scaled) ----
        float mx0 = -1e30f, mx1 = -1e30f;
#pragma unroll
        for (int nf = 0; nf < 8; ++nf) {
            mx0 = fmaxf(mx0, fmaxf(s[nf][0], s[nf][1]));
            mx1 = fmaxf(mx1, fmaxf(s[nf][2], s[nf][3]));
        }
        mx0 = fmaxf(mx0, __shfl_xor_sync(0xffffffffu, mx0, 1));
        mx0 = fmaxf(mx0, __shfl_xor_sync(0xffffffffu, mx0, 2));
        mx1 = fmaxf(mx1, __shfl_xor_sync(0xffffffffu, mx1, 1));
        mx1 = fmaxf(mx1, __shfl_xor_sync(0xffffffffu, mx1, 2));
        float nm0 = fmaxf(m0r, mx0), nm1 = fmaxf(m1r, mx1);
        float sc0 = __expf(m0r - nm0), sc1 = __expf(m1r - nm1);
        m0r = nm0; m1r = nm1;

        float sum0 = 0.f, sum1 = 0.f;
        uint32_t plo[8], phi[8];
#pragma unroll
        for (int nf = 0; nf < 8; ++nf) {
            float p0 = __expf(s[nf][0] - m0r), p1 = __expf(s[nf][1] - m0r);
            float p2 = __expf(s[nf][2] - m1r), p3 = __expf(s[nf][3] - m1r);
            sum0 += p0 + p1; sum1 += p2 + p3;
            plo[nf] = h2u(__floats2half2_rn(p0, p1));
            phi[nf] = h2u(__floats2half2_rn(p2, p3));
        }
        sum0 += __shfl_xor_sync(0xffffffffu, sum0, 1);
        sum0 += __shfl_xor_sync(0xffffffffu, sum0, 2);
        sum1 += __shfl_xor_sync(0xffffffffu, sum1, 1);
        sum1 += __shfl_xor_sync(0xffffffffu, sum1, 2);
        l0 = l0 * sc0 + sum0;
        l1 = l1 * sc1 + sum1;
#pragma unroll
        for (int nf = 0; nf < 16; ++nf) {
            o[nf][0] *= sc0; o[nf][1] *= sc0; o[nf][2] *= sc1; o[nf][3] *= sc1;
        }

        // ---- O += P @ V : P in registers, 2 kv-blocks of 32 ----
#pragma unroll
        for (int blk = 0; blk < 2; ++blk) {
            int c = (blk * 4 + t) ^ swz;
            uint32_t a00 = plo[4*blk],     a01 = phi[4*blk];
            uint32_t a02 = plo[4*blk + 1], a03 = phi[4*blk + 1];
            uint32_t a10 = plo[4*blk + 2], a11 = phi[4*blk + 2];
            uint32_t a12 = plo[4*blk + 3], a13 = phi[4*blk + 3];
#pragma unroll
            for (int nf = 0; nf < 16; ++nf) {
                uint4 vq = Vs4[(nf * 8 + g) * 8 + c];
                mma_f16(o[nf], a00, a01, a02, a03, vq.x, vq.y);
                mma_f16(o[nf], a10, a11, a12, a13, vq.z, vq.w);
            }
        }
    }

    float inv0 = 1.f / l0;
    float inv1 = 1.f / l1;
#pragma unroll
    for (int nf = 0; nf < 16; ++nf) {
        int cpos = h * 128 + (nf >> 2) * 32 + 8 * t + 2 * (nf & 3);
        size_t base0 = ((size_t)(b * M_) + m0 + r0) * 2048 + cpos;
        *(__half2*)&g_AoH[base0] = __floats2half2_rn(o[nf][0] * inv0, o[nf][1] * inv0);
        *(__half2*)&g_AoH[base0 + (size_t)8 * 2048] =
            __floats2half2_rn(o[nf][2] * inv1, o[nf][3] * inv1);
    }
}

// ---------------- launch ----------------
extern "C" void kernel_launch(void* const* d_in, const int* in_sizes, int n_in,
                              void* d_out, int out_size) {
    const float* query = (const float*)d_in[0];
    const float* keyv  = (const float*)d_in[1];
    const float* W_QC  = (const float*)d_in[2];
    const float* W_KC  = (const float*)d_in[3];
    const float* W_QR  = (const float*)d_in[4];
    const float* W_KR  = (const float*)d_in[5];
    const float* W_V   = (const float*)d_in[6];
    const float* W_O   = (const float*)d_in[7];
    float* out = (float*)d_out;

    static __half *pAq = nullptr, *pAkv, *pWqc, *pWkc, *pWqr, *pWkr, *pWv, *pWo;
    static __half *pQf, *pKf, *pVp, *pVt, *pAo;
    if (!pAq) {
        cudaFuncSetAttribute(gemm_h, cudaFuncAttributeMaxDynamicSharedMemorySize, GEMM_SMEM);
        cudaFuncSetAttribute(flash_kernel, cudaFuncAttributeMaxDynamicSharedMemorySize, FLASH_SMEM);
        cudaGetSymbolAddress((void**)&pAq,  g_AqH);
        cudaGetSymbolAddress((void**)&pAkv, g_AkvH);
        cudaGetSymbolAddress((void**)&pWqc, g_WqcH);
        cudaGetSymbolAddress((void**)&pWkc, g_WkcH);
        cudaGetSymbolAddress((void**)&pWqr, g_WqrH);
        cudaGetSymbolAddress((void**)&pWkr, g_WkrH);
        cudaGetSymbolAddress((void**)&pWv,  g_WvH);
        cudaGetSymbolAddress((void**)&pWo,  g_WoH);
        cudaGetSymbolAddress((void**)&pQf,  g_QfH);
        cudaGetSymbolAddress((void**)&pKf,  g_KfH);
        cudaGetSymbolAddress((void**)&pVp,  g_VpH);
        cudaGetSymbolAddress((void**)&pVt,  g_VtH);
        cudaGetSymbolAddress((void**)&pAo,  g_AoH);
    }

    rope_cache_kernel<<<256, 256>>>();

    const int nb_act = B_ * M_ * D_ / 32;
    const int nb_w   = H_ * DH_ * D_ / 32;
    const int nb_wr  = H_ * DR_ * D_ / 32;
    conv_perm_kernel<<<nb_act / 256, 256>>>((const float4*)query, (uint4*)pAq,  nb_act);
    conv_perm_kernel<<<nb_act / 256, 256>>>((const float4*)keyv,  (uint4*)pAkv, nb_act);
    conv_perm_kernel<<<nb_w  / 256, 256>>>((const float4*)W_QC, (uint4*)pWqc, nb_w);
    conv_perm_kernel<<<nb_w  / 256, 256>>>((const float4*)W_KC, (uint4*)pWkc, nb_w);
    conv_perm_kernel<<<nb_wr / 256, 256>>>((const float4*)W_QR, (uint4*)pWqr, nb_wr);
    conv_perm_kernel<<<nb_wr / 256, 256>>>((const float4*)W_KR, (uint4*)pWkr, nb_wr);
    conv_perm_kernel<<<nb_w  / 256, 256>>>((const float4*)W_V,  (uint4*)pWv,  nb_w);
    conv_perm_kernel<<<nb_w  / 256, 256>>>((const float4*)W_O,  (uint4*)pWo,  nb_w);

    dim3 thr(256);
    gemm_h<<<dim3(16, 32), thr, GEMM_SMEM>>>(pAq,  pWqc, pQf, 0, 128, 192, 0,   SCALE_);
    gemm_h<<<dim3(8, 32),  thr, GEMM_SMEM>>>(pAq,  pWqr, pQf, 0, 64, 192, 128,  SCALE_);
    gemm_h<<<dim3(16, 32), thr, GEMM_SMEM>>>(pAkv, pWkc, pKf, 0, 128, 192, 0,   1.0f);
    gemm_h<<<dim3(8, 32),  thr, GEMM_SMEM>>>(pAkv, pWkr, pKf, 0, 64, 192, 128,  1.0f);
    gemm_h<<<dim3(16, 32), thr, GEMM_SMEM>>>(pAkv, pWv,  pVp, 1, 128, 128, 0,   1.0f);
    transpose_v_kernel<<<dim3(4, 64, 32), dim3(32, 8)>>>();
    rope_apply_h<<<8192, 256>>>(pQf);
    rope_apply_h<<<8192, 256>>>(pKf);
    flash_kernel<<<dim3(16, 32), thr, FLASH_SMEM>>>();
    gemm_h<<<dim3(16, 32), thr, GEMM_SMEM>>>(pAo, pWo, out, 2, 1, 2048, 0, 1.0f);
}

// round 12
// speedup vs baseline: 2.2276x; 1.0307x over previous
#include <cuda_runtime.h>
#include <cuda_fp16.h>
#include <cstdint>
#include <math.h>

// Problem constants
#define B_   2
#define M_   2048
#define N_   2048
#define D_   2048
#define H_   16
#define DH_  128
#define DR_  64
#define DQK_ 192
#define SCALE_ 0.07216878364870323f  // 1/sqrt(192)

// ---------------- scratch (allocation-free: __device__ globals) ----------------
__device__ __half g_AqH [(size_t)B_ * M_ * D_];
__device__ __half g_AkvH[(size_t)B_ * N_ * D_];
__device__ __half g_WqcH[(size_t)H_ * DH_ * D_];
__device__ __half g_WkcH[(size_t)H_ * DH_ * D_];
__device__ __half g_WqrH[(size_t)H_ * DR_ * D_];
__device__ __half g_WkrH[(size_t)H_ * DR_ * D_];
__device__ __half g_WvH [(size_t)H_ * DH_ * D_];
__device__ __half g_WoH [(size_t)D_ * H_ * DH_];
__device__ __half g_QfH [(size_t)B_ * H_ * M_ * DQK_]; // perm-d, pre-scaled
__device__ __half g_KfH [(size_t)B_ * H_ * N_ * DQK_];
__device__ __half g_VpH [(size_t)B_ * H_ * N_ * DH_];
__device__ __half g_VtH [(size_t)B_ * H_ * DH_ * N_];  // (b,h,d,n), n perm
__device__ __half g_AoH [(size_t)B_ * M_ * (H_ * DH_)];
__device__ float g_cos[M_ * 32];
__device__ float g_sin[M_ * 32];

// ---------------- small PTX helpers ----------------
__device__ __forceinline__ void cp_async16h(__half* smem, const __half* gmem) {
    uint32_t s = (uint32_t)__cvta_generic_to_shared(smem);
    asm volatile("cp.async.cg.shared.global [%0], [%1], 16;\n" :: "r"(s), "l"(gmem) : "memory");
}
__device__ __forceinline__ void cp_commit() { asm volatile("cp.async.commit_group;\n" ::: "memory"); }
template <int N> __device__ __forceinline__ void cp_wait() {
    asm volatile("cp.async.wait_group %0;\n" :: "n"(N) : "memory");
}
__device__ __forceinline__ void mma_f16(float c[4],
        uint32_t a0, uint32_t a1, uint32_t a2, uint32_t a3,
        uint32_t b0, uint32_t b1) {
    asm volatile(
        "mma.sync.aligned.m16n8k16.row.col.f32.f16.f16.f32 "
        "{%0,%1,%2,%3},{%4,%5,%6,%7},{%8,%9},{%0,%1,%2,%3};\n"
        : "+f"(c[0]), "+f"(c[1]), "+f"(c[2]), "+f"(c[3])
        : "r"(a0), "r"(a1), "r"(a2), "r"(a3), "r"(b0), "r"(b1));
}
__device__ __forceinline__ uint32_t h2u(__half2 h) { return *(uint32_t*)&h; }
__device__ __forceinline__ int posk(int k) {
    return ((k >> 1) & 3) * 8 + ((k >> 3) & 3) * 2 + (k & 1);
}

// ---------------- fused fp32 -> fp16 convert (all 8 tensors, one kernel) ----------------
#define NBA 262144
#define NBW 131072
#define NBR 65536
#define NB_TOT (2 * NBA + 4 * NBW + 2 * NBR)   // 1179648

__global__ void conv_all(const float4* __restrict__ q,   const float4* __restrict__ kv,
                         const float4* __restrict__ wqc, const float4* __restrict__ wkc,
                         const float4* __restrict__ wv,  const float4* __restrict__ wo,
                         const float4* __restrict__ wqr, const float4* __restrict__ wkr) {
    int i = blockIdx.x * blockDim.x + threadIdx.x;
    if (i >= NB_TOT) return;
    const float4* s; uint4* d; int o = i;
    if (o < NBA)              { s = q;   d = (uint4*)g_AqH; }
    else if ((o -= NBA) < NBA){ s = kv;  d = (uint4*)g_AkvH; }
    else if ((o -= NBA) < NBW){ s = wqc; d = (uint4*)g_WqcH; }
    else if ((o -= NBW) < NBW){ s = wkc; d = (uint4*)g_WkcH; }
    else if ((o -= NBW) < NBW){ s = wv;  d = (uint4*)g_WvH; }
    else if ((o -= NBW) < NBW){ s = wo;  d = (uint4*)g_WoH; }
    else if ((o -= NBW) < NBR){ s = wqr; d = (uint4*)g_WqrH; }
    else { o -= NBR;            s = wkr; d = (uint4*)g_WkrH; }

    float v[32];
    const float4* sp = s + (size_t)o * 8;
#pragma unroll
    for (int j = 0; j < 8; ++j) {
        float4 f = sp[j];
        v[4*j] = f.x; v[4*j+1] = f.y; v[4*j+2] = f.z; v[4*j+3] = f.w;
    }
    uint4* dp = d + (size_t)o * 4;
#pragma unroll
    for (int t = 0; t < 4; ++t) {
        uint32_t h[4];
#pragma unroll
        for (int jj = 0; jj < 4; ++jj) {
            int k = 2 * t + 8 * jj;
            h[jj] = h2u(__floats2half2_rn(v[k], v[k + 1]));
        }
        dp[t] = make_uint4(h[0], h[1], h[2], h[3]);
    }
}

// ---------------- RoPE cache + apply (both Q and K in one launch) ----------------
__global__ void rope_cache_kernel() {
    int idx = blockIdx.x * blockDim.x + threadIdx.x;
    if (idx >= M_ * 32) return;
    int s = idx >> 5, i = idx & 31;
    double e = (double)(2 * i) / 64.0;
    float freq = (float)(1.0 / pow(1000000.0, e));
    float ang = (float)s * freq;
    double a = (double)ang;
    g_cos[idx] = (float)cos(a);
    g_sin[idx] = (float)sin(a);
}

#define ROPE_HALF (B_ * H_ * M_ * 32)
__global__ void rope_apply2() {
    int idx = blockIdx.x * blockDim.x + threadIdx.x;
    __half* buf;
    if (idx < ROPE_HALF) buf = g_QfH;
    else { idx -= ROPE_HALF; buf = g_KfH; }
    int i5 = idx & 31;
    int s = (idx >> 5) & (M_ - 1);
    int bh = idx >> 16;
    int blk = i5 >> 4, pp = i5 & 15;
    int qd = (pp >> 2) + ((pp & 3) << 2);
    int fi = blk * 16 + qd;
    size_t base = ((size_t)bh * M_ + s) * DQK_ + DH_ + blk * 32 + 2 * pp;
    float c = g_cos[(s << 5) + fi], sn = g_sin[(s << 5) + fi];
    __half2 xv = *(__half2*)(buf + base);
    float x0 = __low2float(xv), x1 = __high2float(xv);
    *(__half2*)(buf + base) = __floats2half2_rn(x0 * c - x1 * sn, x1 * c + x0 * sn);
}

// ---------------- V transpose: (b,h,n,d) -> (b,h,d,n) with n permuted ----------------
__global__ void transpose_v_kernel() {
    __shared__ __half ts[32][33];
    int bh = blockIdx.z;
    int d0 = blockIdx.x * 32, n0 = blockIdx.y * 32;
    const __half* src = g_VpH + (size_t)bh * N_ * DH_;
    __half* dst = g_VtH + (size_t)bh * DH_ * N_;
    int tx = threadIdx.x, ty = threadIdx.y;
#pragma unroll
    for (int i = 0; i < 32; i += 8)
        ts[ty + i][tx] = src[(size_t)(n0 + ty + i) * DH_ + d0 + tx];
    __syncthreads();
    int pn = posk(tx);
#pragma unroll
    for (int i = 0; i < 32; i += 8)
        dst[(size_t)(d0 + ty + i) * N_ + n0 + pn] = ts[tx][ty + i];
}

// ---------------- fp16 GEMM: C = A @ W^T, tile 128x128x32, warp 64x64, 1 bar/ktile ----------------
#define G_ASZ 4096                              // halves per stage per operand
#define G_STG 4
#define GEMM_SMEM (G_STG * 2 * G_ASZ * 2)       // 65536 B

__global__ __launch_bounds__(128, 2)
void gemm_h(const __half* __restrict__ A, const __half* __restrict__ W,
            void* __restrict__ Cout, int mode, int dh, int ld, int off, float es) {
    extern __shared__ __half smh[];
    __half* smA = smh;
    __half* smB = smh + G_STG * G_ASZ;

    const int tid = threadIdx.x;
    const int m0 = blockIdx.y * 128;
    const int n0 = blockIdx.x * 128;
    const __half* Ab = A + (size_t)m0 * D_;
    const __half* Wb = W + (size_t)n0 * D_;

    auto load_stage = [&](int kt, int s) {
        const int k0 = kt * 32;
        __half* sa = smA + s * G_ASZ;
        __half* sb = smB + s * G_ASZ;
#pragma unroll
        for (int i = 0; i < 4; ++i) {
            int c = tid + i * 128;
            int row = c >> 2, t4 = c & 3;
            cp_async16h(sa + row * 32 + t4 * 8, Ab + (size_t)row * D_ + k0 + t4 * 8);
        }
#pragma unroll
        for (int i = 0; i < 4; ++i) {
            int c = tid + i * 128;
            int row = c >> 2, t4 = c & 3;
            cp_async16h(sb + row * 32 + t4 * 8, Wb + (size_t)row * D_ + k0 + t4 * 8);
        }
        cp_commit();
    };

    float acc[4][8][4] = {};
    const int warp = tid >> 5, lane = tid & 31;
    const int wm = warp >> 1, wn = warp & 1;   // 2x2 warps, warp tile 64x64
    const int g = lane >> 2, t = lane & 3;

    load_stage(0, 0); load_stage(1, 1); load_stage(2, 2);
    const int NKT = D_ / 32;   // 64
    for (int kt = 0; kt < NKT; ++kt) {
        // single barrier per k-tile; prefetch issued AFTER barrier -> overwrite-safe
        if (kt + 3 < NKT)      { cp_wait<2>(); __syncthreads(); load_stage(kt + 3, (kt + 3) & 3); }
        else if (kt + 2 < NKT) { cp_wait<2>(); __syncthreads(); }
        else if (kt + 1 < NKT) { cp_wait<1>(); __syncthreads(); }
        else                   { cp_wait<0>(); __syncthreads(); }

        const uint4* sa = (const uint4*)(smA + (kt & 3) * G_ASZ);
        const uint4* sb = (const uint4*)(smB + (kt & 3) * G_ASZ);
        uint4 af[4][2];
#pragma unroll
        for (int im = 0; im < 4; ++im) {
            int r = wm * 64 + im * 16 + g;
            af[im][0] = sa[r * 4 + t];
            af[im][1] = sa[(r + 8) * 4 + t];
        }
#pragma unroll
        for (int in = 0; in < 8; ++in) {
            uint4 bq = sb[(wn * 64 + in * 8 + g) * 4 + t];
#pragma unroll
            for (int im = 0; im < 4; ++im) {
                mma_f16(acc[im][in], af[im][0].x, af[im][1].x, af[im][0].y, af[im][1].y, bq.x, bq.y);
                mma_f16(acc[im][in], af[im][0].z, af[im][1].z, af[im][0].w, af[im][1].w, bq.z, bq.w);
            }
        }
    }

#pragma unroll
    for (int im = 0; im < 4; ++im) {
        int r0g = m0 + wm * 64 + im * 16 + g;
#pragma unroll
        for (int in = 0; in < 8; ++in) {
            int c0 = n0 + wn * 64 + in * 8 + 2 * t;
            if (mode == 2) {
                float* C = (float*)Cout;
                *(float2*)&C[(size_t)r0g * 2048 + c0] =
                    make_float2(acc[im][in][0], acc[im][in][1]);
                *(float2*)&C[(size_t)(r0g + 8) * 2048 + c0] =
                    make_float2(acc[im][in][2], acc[im][in][3]);
            } else {
                __half* C = (__half*)Cout;
                int b = r0g >> 11, m = r0g & (M_ - 1);
                int h = c0 / dh, d = c0 - h * dh;
                int dcol = (mode == 0) ? ((d & ~31) + posk(d & 31)) : d;
                size_t base = (((size_t)(b * H_ + h) * M_) + m) * ld + off + dcol;
                *(__half2*)&C[base] = __floats2half2_rn(acc[im][in][0] * es, acc[im][in][1] * es);
                *(__half2*)&C[base + (size_t)8 * ld] =
                    __floats2half2_rn(acc[im][in][2] * es, acc[im][in][3] * es);
            }
        }
    }
}

// ---------------- fused flash attention fp16 (Br=64, Bc=64, 4 warps, 2 CTA/SM) ----------------
// halves: Q 64x192 | K 2x 64x192 | V 2x 128x64 = 53248 halves = 106496 B
#define FL_KOFF 12288
#define FL_VOFF 36864
#define FLASH_SMEM (53248 * 2)

__global__ __launch_bounds__(128, 2)
void flash_kernel() {
    extern __shared__ __half smh[];
    __half* Qs = smh;
    __half* Ks = smh + FL_KOFF;
    __half* Vs = smh + FL_VOFF;

    const int tid = threadIdx.x;
    const int m0 = blockIdx.x * 64;
    const int bh = blockIdx.y;
    const int b = bh >> 4, h = bh & 15;

    const __half* Qg = g_QfH + ((size_t)bh * M_ + m0) * DQK_;
    const __half* Kg = g_KfH + (size_t)bh * N_ * DQK_;
    const __half* Vg = g_VtH + (size_t)bh * DH_ * N_;

    // Q: 64x192, swizzled chunks
#pragma unroll
    for (int i = 0; i < 12; ++i) {
        int c = tid + i * 128;
        int row = c / 24, cc = c % 24;
        int phys = cc ^ ((row & 1) << 2);
        cp_async16h(Qs + row * 192 + phys * 8, Qg + (size_t)row * 192 + cc * 8);
    }
    cp_commit();

    auto load_K = [&](int j, int buf) {
        const __half* src = Kg + (size_t)j * 64 * DQK_;
        __half* dst = Ks + buf * 12288;
#pragma unroll
        for (int i = 0; i < 12; ++i) {
            int c = tid + i * 128;
            int row = c / 24, cc = c % 24;
            int phys = cc ^ ((row & 1) << 2);
            cp_async16h(dst + row * 192 + phys * 8, src + (size_t)row * 192 + cc * 8);
        }
        cp_commit();
    };
    auto load_V = [&](int j, int buf) {
        __half* dst = Vs + buf * 8192;
#pragma unroll
        for (int i = 0; i < 8; ++i) {
            int c = tid + i * 128;
            int row = c >> 3, cc = c & 7;
            int phys = cc ^ ((row & 1) << 2);
            cp_async16h(dst + row * 64 + phys * 8, Vg + (size_t)row * N_ + j * 64 + cc * 8);
        }
        cp_commit();
    };

    load_K(0, 0);
    load_V(0, 0);

    const int warp = tid >> 5, lane = tid & 31;
    const int g = lane >> 2, t = lane & 3;
    const int r0 = warp * 16 + g;              // warp owns rows r0, r0+8
    const int swz = (g & 1) << 2;
    const int qr0 = r0 * 24, qr1 = (r0 + 8) * 24;

    float o[16][4] = {};
    float m0r = -1e30f, m1r = -1e30f, l0 = 0.f, l1 = 0.f;

    for (int j = 0; j < N_ / 64; ++j) {
        cp_wait<0>();
        __syncthreads();
        if (j + 1 < N_ / 64) { load_K(j + 1, (j + 1) & 1); load_V(j + 1, (j + 1) & 1); }

        const uint4* Ks4 = (const uint4*)(Ks + (j & 1) * 12288);
        const uint4* Vs4 = (const uint4*)(Vs + (j & 1) * 8192);
        const uint4* Qs4 = (const uint4*)Qs;

        // ---- S = Q K^T : warp tile 16x64, 6 k-blocks of 32 ----
        float s[8][4] = {};
#pragma unroll
        for (int blk = 0; blk < 6; ++blk) {
            int c = (blk * 4 + t) ^ swz;
            uint4 q0 = Qs4[qr0 + c];
            uint4 q1 = Qs4[qr1 + c];
#pragma unroll
            for (int nf = 0; nf < 8; ++nf) {
                uint4 kq = Ks4[(nf * 8 + g) * 24 + c];
                mma_f16(s[nf], q0.x, q1.x, q0.y, q1.y, kq.x, kq.y);
                mma_f16(s[nf], q0.z, q1.z, q0.w, q1.w, kq.z, kq.w);
            }
        }

        // ---- warp-local online softmax (Q pre-scaled) ----
        float mx0 = -1e30f, mx1 = -1e30f;
#pragma unroll
        for (int nf = 0; nf < 8; ++nf) {
            mx0 = fmaxf(mx0, fmaxf(s[nf][0], s[nf][1]));
            mx1 = fmaxf(mx1, fmaxf(s[nf][2], s[nf][3]));
        }
        mx0 = fmaxf(mx0, __shfl_xor_sync(0xffffffffu, mx0, 1));
        mx0 = fmaxf(mx0, __shfl_xor_sync(0xffffffffu, mx0, 2));
        mx1 = fmaxf(mx1, __shfl_xor_sync(0xffffffffu, mx1, 1));
        mx1 = fmaxf(mx1, __shfl_xor_sync(0xffffffffu, mx1, 2));
        float nm0 = fmaxf(m0r, mx0), nm1 = fmaxf(m1r, mx1);
        float sc0 = __expf(m0r - nm0), sc1 = __expf(m1r - nm1);
        m0r = nm0; m1r = nm1;

        float sum0 = 0.f, sum1 = 0.f;
        uint32_t plo[8], phi[8];
#pragma unroll
        for (int nf = 0; nf < 8; ++nf) {
            float p0 = __expf(s[nf][0] - m0r), p1 = __expf(s[nf][1] - m0r);
            float p2 = __expf(s[nf][2] - m1r), p3 = __expf(s[nf][3] - m1r);
            sum0 += p0 + p1; sum1 += p2 + p3;
            plo[nf] = h2u(__floats2half2_rn(p0, p1));
            phi[nf] = h2u(__floats2half2_rn(p2, p3));
        }
        sum0 += __shfl_xor_sync(0xffffffffu, sum0, 1);
        sum0 += __shfl_xor_sync(0xffffffffu, sum0, 2);
        sum1 += __shfl_xor_sync(0xffffffffu, sum1, 1);
        sum1 += __shfl_xor_sync(0xffffffffu, sum1, 2);
        l0 = l0 * sc0 + sum0;
        l1 = l1 * sc1 + sum1;
#pragma unroll
        for (int nf = 0; nf < 16; ++nf) {
            o[nf][0] *= sc0; o[nf][1] *= sc0; o[nf][2] *= sc1; o[nf][3] *= sc1;
        }

        // ---- O += P @ V : P in registers, 2 kv-blocks of 32 ----
#pragma unroll
        for (int blk = 0; blk < 2; ++blk) {
            int c = (blk * 4 + t) ^ swz;
            uint32_t a00 = plo[4*blk],     a01 = phi[4*blk];
            uint32_t a02 = plo[4*blk + 1], a03 = phi[4*blk + 1];
            uint32_t a10 = plo[4*blk + 2], a11 = phi[4*blk + 2];
            uint32_t a12 = plo[4*blk + 3], a13 = phi[4*blk + 3];
#pragma unroll
            for (int nf = 0; nf < 16; ++nf) {
                uint4 vq = Vs4[(nf * 8 + g) * 8 + c];
                mma_f16(o[nf], a00, a01, a02, a03, vq.x, vq.y);
                mma_f16(o[nf], a10, a11, a12, a13, vq.z, vq.w);
            }
        }
    }

    float inv0 = 1.f / l0;
    float inv1 = 1.f / l1;
#pragma unroll
    for (int nf = 0; nf < 16; ++nf) {
        int cpos = h * 128 + (nf >> 2) * 32 + 8 * t + 2 * (nf & 3);
        size_t base0 = ((size_t)(b * M_) + m0 + r0) * 2048 + cpos;
        *(__half2*)&g_AoH[base0] = __floats2half2_rn(o[nf][0] * inv0, o[nf][1] * inv0);
        *(__half2*)&g_AoH[base0 + (size_t)8 * 2048] =
            __floats2half2_rn(o[nf][2] * inv1, o[nf][3] * inv1);
    }
}

// ---------------- launch ----------------
extern "C" void kernel_launch(void* const* d_in, const int* in_sizes, int n_in,
                              void* d_out, int out_size) {
    const float* query = (const float*)d_in[0];
    const float* keyv  = (const float*)d_in[1];
    const float* W_QC  = (const float*)d_in[2];
    const float* W_KC  = (const float*)d_in[3];
    const float* W_QR  = (const float*)d_in[4];
    const float* W_KR  = (const float*)d_in[5];
    const float* W_V   = (const float*)d_in[6];
    const float* W_O   = (const float*)d_in[7];
    float* out = (float*)d_out;

    static __half *pAq = nullptr, *pAkv, *pWqc, *pWkc, *pWqr, *pWkr, *pWv, *pWo;
    static __half *pQf, *pKf, *pVp, *pAo;
    if (!pAq) {
        cudaFuncSetAttribute(gemm_h, cudaFuncAttributeMaxDynamicSharedMemorySize, GEMM_SMEM);
        cudaFuncSetAttribute(flash_kernel, cudaFuncAttributeMaxDynamicSharedMemorySize, FLASH_SMEM);
        cudaGetSymbolAddress((void**)&pAq,  g_AqH);
        cudaGetSymbolAddress((void**)&pAkv, g_AkvH);
        cudaGetSymbolAddress((void**)&pWqc, g_WqcH);
        cudaGetSymbolAddress((void**)&pWkc, g_WkcH);
        cudaGetSymbolAddress((void**)&pWqr, g_WqrH);
        cudaGetSymbolAddress((void**)&pWkr, g_WkrH);
        cudaGetSymbolAddress((void**)&pWv,  g_WvH);
        cudaGetSymbolAddress((void**)&pWo,  g_WoH);
        cudaGetSymbolAddress((void**)&pQf,  g_QfH);
        cudaGetSymbolAddress((void**)&pKf,  g_KfH);
        cudaGetSymbolAddress((void**)&pVp,  g_VpH);
        cudaGetSymbolAddress((void**)&pAo,  g_AoH);
    }

    rope_cache_kernel<<<256, 256>>>();

    conv_all<<<(NB_TOT + 255) / 256, 256>>>(
        (const float4*)query, (const float4*)keyv,
        (const float4*)W_QC, (const float4*)W_KC,
        (const float4*)W_V,  (const float4*)W_O,
        (const float4*)W_QR, (const float4*)W_KR);

    dim3 thr(128);
    gemm_h<<<dim3(16, 32), thr, GEMM_SMEM>>>(pAq,  pWqc, pQf, 0, 128, 192, 0,   SCALE_);
    gemm_h<<<dim3(8, 32),  thr, GEMM_SMEM>>>(pAq,  pWqr, pQf, 0, 64, 192, 128,  SCALE_);
    gemm_h<<<dim3(16, 32), thr, GEMM_SMEM>>>(pAkv, pWkc, pKf, 0, 128, 192, 0,   1.0f);
    gemm_h<<<dim3(8, 32),  thr, GEMM_SMEM>>>(pAkv, pWkr, pKf, 0, 64, 192, 128,  1.0f);
    gemm_h<<<dim3(16, 32), thr, GEMM_SMEM>>>(pAkv, pWv,  pVp, 1, 128, 128, 0,   1.0f);
    transpose_v_kernel<<<dim3(4, 64, 32), dim3(32, 8)>>>();
    rope_apply2<<<2 * ROPE_HALF / 256, 256>>>();
    flash_kernel<<<dim3(32, 32), thr, FLASH_SMEM>>>();
    gemm_h<<<dim3(16, 32), thr, GEMM_SMEM>>>(pAo, pWo, out, 2, 1, 2048, 0, 1.0f);
}